// round 1
// baseline (speedup 1.0000x reference)
#include <cuda_runtime.h>
#include <math.h>

// Problem constants
#define NB     16
#define NC     512
#define NHW    1024
#define NHEADS 8
#define ND     64
#define QC     1536     // 3*NC
#define GN_EPS 1e-5f

// Scratch (device globals — no allocation allowed)
__device__ float g_xn [NB * NC * NHW];   // 32 MB: groupnorm output
__device__ float g_qkv[NB * QC * NHW];   // 96 MB: qkv, layout [b][o][n], o in [0,1536)
__device__ float g_ao [NB * NC * NHW];   // 32 MB: attention output (pre-proj)

// ---------------------------------------------------------------------------
// Kernel 1: GroupNorm (groups = 8, each group = 64 channels x 1024 spatial,
// contiguous 65536-float region). One block per (b, g).
// ---------------------------------------------------------------------------
__global__ __launch_bounds__(512) void gn_kernel(const float* __restrict__ x,
                                                 const float* __restrict__ gw,
                                                 const float* __restrict__ gb) {
    int bg = blockIdx.x;
    int b = bg >> 3, g = bg & 7;
    const float4* xp = (const float4*)(x + (size_t)(b * NC + g * 64) * NHW);
    float4* op = (float4*)(g_xn + (size_t)(b * NC + g * 64) * NHW);
    const int NE4 = 64 * NHW / 4;  // 16384 float4
    int tid = threadIdx.x;

    float s = 0.f, s2 = 0.f;
    for (int i = tid; i < NE4; i += 512) {
        float4 v = xp[i];
        s  += v.x + v.y + v.z + v.w;
        s2 += v.x * v.x + v.y * v.y + v.z * v.z + v.w * v.w;
    }
    // block reduction
    __shared__ float rs[16], rs2[16];
    #pragma unroll
    for (int o = 16; o > 0; o >>= 1) {
        s  += __shfl_down_sync(0xFFFFFFFFu, s, o);
        s2 += __shfl_down_sync(0xFFFFFFFFu, s2, o);
    }
    int w = tid >> 5, l = tid & 31;
    if (l == 0) { rs[w] = s; rs2[w] = s2; }
    __syncthreads();
    __shared__ float sh_mean, sh_rstd;
    if (tid == 0) {
        float S = 0.f, S2 = 0.f;
        #pragma unroll
        for (int i = 0; i < 16; i++) { S += rs[i]; S2 += rs2[i]; }
        float mean = S * (1.f / 65536.f);
        float var  = S2 * (1.f / 65536.f) - mean * mean;
        sh_mean = mean;
        sh_rstd = rsqrtf(var + GN_EPS);
    }
    __syncthreads();
    float mean = sh_mean, rstd = sh_rstd;
    for (int i = tid; i < NE4; i += 512) {
        int c = g * 64 + (i >> 8);           // i/256 float4 per channel row
        float sc = gw[c] * rstd;
        float bi = gb[c] - mean * sc;
        float4 v = xp[i];
        v.x = v.x * sc + bi; v.y = v.y * sc + bi;
        v.z = v.z * sc + bi; v.w = v.w * sc + bi;
        op[i] = v;
    }
}

// ---------------------------------------------------------------------------
// Kernel 2: QKV 1x1 conv = batched GEMM. out[b][o][n] = sum_c W[o][c]*xn[b][c][n] + bias[o]
// Block computes 64(o) x 64(n) tile; 256 threads, 4x4 register tile, K-chunks of 16.
// ---------------------------------------------------------------------------
__global__ __launch_bounds__(256) void qkv_gemm(const float* __restrict__ W,
                                                const float* __restrict__ bias) {
    __shared__ float  As[16][65];   // [k][o], padded (conflict-free store & read)
    __shared__ float4 Bs[16][16];   // [k][n/4]
    int tid = threadIdx.x;
    int tx = tid & 15, ty = tid >> 4;
    int n0 = blockIdx.x * 64;
    int o0 = blockIdx.y * 64;
    int b  = blockIdx.z;
    const float* In = g_xn + (size_t)b * NC * NHW;
    int lo = tid >> 4, lk = tid & 15;

    float acc[4][4] = {};
    for (int k0 = 0; k0 < NC; k0 += 16) {
        #pragma unroll
        for (int it = 0; it < 4; it++)
            As[lk][lo + it * 16] = W[(size_t)(o0 + lo + it * 16) * NC + k0 + lk];
        Bs[ty][tx] = *(const float4*)&In[(size_t)(k0 + ty) * NHW + n0 + tx * 4];
        __syncthreads();
        #pragma unroll
        for (int kk = 0; kk < 16; kk++) {
            float a0 = As[kk][ty * 4 + 0], a1 = As[kk][ty * 4 + 1];
            float a2 = As[kk][ty * 4 + 2], a3 = As[kk][ty * 4 + 3];
            float4 bv = Bs[kk][tx];
            acc[0][0] += a0 * bv.x; acc[0][1] += a0 * bv.y; acc[0][2] += a0 * bv.z; acc[0][3] += a0 * bv.w;
            acc[1][0] += a1 * bv.x; acc[1][1] += a1 * bv.y; acc[1][2] += a1 * bv.z; acc[1][3] += a1 * bv.w;
            acc[2][0] += a2 * bv.x; acc[2][1] += a2 * bv.y; acc[2][2] += a2 * bv.z; acc[2][3] += a2 * bv.w;
            acc[3][0] += a3 * bv.x; acc[3][1] += a3 * bv.y; acc[3][2] += a3 * bv.z; acc[3][3] += a3 * bv.w;
        }
        __syncthreads();
    }
    float* outp = g_qkv + (size_t)b * QC * NHW;
    #pragma unroll
    for (int ii = 0; ii < 4; ii++) {
        int o = o0 + ty * 4 + ii;
        float bi = bias[o];
        float4 rv = make_float4(acc[ii][0] + bi, acc[ii][1] + bi,
                                acc[ii][2] + bi, acc[ii][3] + bi);
        *(float4*)&outp[(size_t)o * NHW + n0 + tx * 4] = rv;
    }
}

// ---------------------------------------------------------------------------
// Kernel 3: fused flash attention per (b, h, 64-query tile).
// Q,K,V stored d-major [dd][n]. S[nq][mk] = sum_dd Q[dd][nq]*K[dd][mk] (Q pre-scaled).
// Online softmax; O[dd][nq] accumulated in registers (4x4 per thread).
// ---------------------------------------------------------------------------
#define SROW 68
#define ATTN_SMEM ((4 * 64 * SROW + 256 + 3 * 64) * 4)

__global__ __launch_bounds__(256) void attn_kernel() {
    extern __shared__ float sm[];
    float* Qs   = sm;                 // [64][SROW]
    float* Ks   = Qs + 64 * SROW;
    float* Vs   = Ks + 64 * SROW;
    float* Ss   = Vs + 64 * SROW;
    float* red  = Ss + 64 * SROW;     // [4][64]
    float* m_s  = red + 256;
    float* l_s  = m_s + 64;
    float* al_s = l_s + 64;

    int tid = threadIdx.x;
    int tx = tid & 15, ty = tid >> 4;
    int qt = blockIdx.x, h = blockIdx.y, b = blockIdx.z;

    const float* qb = g_qkv + ((size_t)b * QC + h * ND) * NHW + qt * 64;
    const float* kb = g_qkv + ((size_t)b * QC + NC + h * ND) * NHW;
    const float* vb = g_qkv + ((size_t)b * QC + 2 * NC + h * ND) * NHW;

    // Load Q tile (pre-scaled by 1/sqrt(d) = 0.125)
    #pragma unroll
    for (int it = 0; it < 4; it++) {
        int i = tid + it * 256;
        int dd = i >> 4, c4 = i & 15;
        float4 v = *(const float4*)&qb[(size_t)dd * NHW + c4 * 4];
        v.x *= 0.125f; v.y *= 0.125f; v.z *= 0.125f; v.w *= 0.125f;
        *(float4*)&Qs[dd * SROW + c4 * 4] = v;
    }
    if (tid < 64) { m_s[tid] = -1e30f; l_s[tid] = 0.f; }

    float o[4][4] = {};
    int r = tid & 63, seg = tid >> 6;

    for (int mt = 0; mt < 16; mt++) {
        __syncthreads();   // prev PV done before overwriting K/V/S
        const float* kp = kb + mt * 64;
        const float* vp = vb + mt * 64;
        #pragma unroll
        for (int it = 0; it < 4; it++) {
            int i = tid + it * 256;
            int dd = i >> 4, c4 = i & 15;
            *(float4*)&Ks[dd * SROW + c4 * 4] = *(const float4*)&kp[(size_t)dd * NHW + c4 * 4];
            *(float4*)&Vs[dd * SROW + c4 * 4] = *(const float4*)&vp[(size_t)dd * NHW + c4 * 4];
        }
        __syncthreads();

        // S = Q^T K   (thread tile: nq = ty*4+ii, mk = tx*4+jj)
        float s[4][4] = {};
        #pragma unroll 8
        for (int dd = 0; dd < 64; dd++) {
            float4 qa = *(const float4*)&Qs[dd * SROW + ty * 4];
            float4 kv = *(const float4*)&Ks[dd * SROW + tx * 4];
            s[0][0] += qa.x * kv.x; s[0][1] += qa.x * kv.y; s[0][2] += qa.x * kv.z; s[0][3] += qa.x * kv.w;
            s[1][0] += qa.y * kv.x; s[1][1] += qa.y * kv.y; s[1][2] += qa.y * kv.z; s[1][3] += qa.y * kv.w;
            s[2][0] += qa.z * kv.x; s[2][1] += qa.z * kv.y; s[2][2] += qa.z * kv.z; s[2][3] += qa.z * kv.w;
            s[3][0] += qa.w * kv.x; s[3][1] += qa.w * kv.y; s[3][2] += qa.w * kv.z; s[3][3] += qa.w * kv.w;
        }
        #pragma unroll
        for (int ii = 0; ii < 4; ii++)
            *(float4*)&Ss[(ty * 4 + ii) * SROW + tx * 4] =
                make_float4(s[ii][0], s[ii][1], s[ii][2], s[ii][3]);
        __syncthreads();

        // row-wise online softmax: 4 threads per row
        float pm = -1e30f;
        #pragma unroll
        for (int j = 0; j < 16; j++) pm = fmaxf(pm, Ss[r * SROW + seg * 16 + j]);
        red[seg * 64 + r] = pm;
        __syncthreads();
        if (tid < 64) {
            float tm = fmaxf(fmaxf(red[tid], red[64 + tid]),
                             fmaxf(red[128 + tid], red[192 + tid]));
            float nm = fmaxf(m_s[tid], tm);
            float al = __expf(m_s[tid] - nm);
            al_s[tid] = al;
            l_s[tid] *= al;
            m_s[tid] = nm;
        }
        __syncthreads();
        float mr = m_s[r];
        float ps = 0.f;
        #pragma unroll
        for (int j = 0; j < 16; j++) {
            float p = __expf(Ss[r * SROW + seg * 16 + j] - mr);
            Ss[r * SROW + seg * 16 + j] = p;
            ps += p;
        }
        red[seg * 64 + r] = ps;
        __syncthreads();
        if (tid < 64)
            l_s[tid] += red[tid] + red[64 + tid] + red[128 + tid] + red[192 + tid];

        // rescale accumulators (O thread tile: dd = ty*4+ii, nq = jj*16+tx)
        #pragma unroll
        for (int jj = 0; jj < 4; jj++) {
            float al = al_s[jj * 16 + tx];
            o[0][jj] *= al; o[1][jj] *= al; o[2][jj] *= al; o[3][jj] *= al;
        }
        // O += P V^T
        #pragma unroll 4
        for (int m4 = 0; m4 < 16; m4++) {
            float4 vv[4], pp[4];
            #pragma unroll
            for (int ii = 0; ii < 4; ii++)
                vv[ii] = *(const float4*)&Vs[(ty * 4 + ii) * SROW + m4 * 4];
            #pragma unroll
            for (int jj = 0; jj < 4; jj++)
                pp[jj] = *(const float4*)&Ss[(jj * 16 + tx) * SROW + m4 * 4];
            #pragma unroll
            for (int ii = 0; ii < 4; ii++)
                #pragma unroll
                for (int jj = 0; jj < 4; jj++)
                    o[ii][jj] += pp[jj].x * vv[ii].x + pp[jj].y * vv[ii].y +
                                 pp[jj].z * vv[ii].z + pp[jj].w * vv[ii].w;
        }
    }
    __syncthreads();   // l_s final visible to all

    float* op = g_ao + ((size_t)b * NC + h * ND) * NHW + qt * 64;
    #pragma unroll
    for (int jj = 0; jj < 4; jj++) {
        float linv = 1.f / l_s[jj * 16 + tx];
        #pragma unroll
        for (int ii = 0; ii < 4; ii++)
            op[(size_t)(ty * 4 + ii) * NHW + jj * 16 + tx] = o[ii][jj] * linv;
    }
}

// ---------------------------------------------------------------------------
// Kernel 4: proj GEMM + bias + residual -> d_out
// ---------------------------------------------------------------------------
__global__ __launch_bounds__(256) void proj_gemm(const float* __restrict__ W,
                                                 const float* __restrict__ bias,
                                                 const float* __restrict__ x,
                                                 float* __restrict__ out) {
    __shared__ float  As[16][65];
    __shared__ float4 Bs[16][16];
    int tid = threadIdx.x;
    int tx = tid & 15, ty = tid >> 4;
    int n0 = blockIdx.x * 64;
    int o0 = blockIdx.y * 64;
    int b  = blockIdx.z;
    const float* In = g_ao + (size_t)b * NC * NHW;
    int lo = tid >> 4, lk = tid & 15;

    float acc[4][4] = {};
    for (int k0 = 0; k0 < NC; k0 += 16) {
        #pragma unroll
        for (int it = 0; it < 4; it++)
            As[lk][lo + it * 16] = W[(size_t)(o0 + lo + it * 16) * NC + k0 + lk];
        Bs[ty][tx] = *(const float4*)&In[(size_t)(k0 + ty) * NHW + n0 + tx * 4];
        __syncthreads();
        #pragma unroll
        for (int kk = 0; kk < 16; kk++) {
            float a0 = As[kk][ty * 4 + 0], a1 = As[kk][ty * 4 + 1];
            float a2 = As[kk][ty * 4 + 2], a3 = As[kk][ty * 4 + 3];
            float4 bv = Bs[kk][tx];
            acc[0][0] += a0 * bv.x; acc[0][1] += a0 * bv.y; acc[0][2] += a0 * bv.z; acc[0][3] += a0 * bv.w;
            acc[1][0] += a1 * bv.x; acc[1][1] += a1 * bv.y; acc[1][2] += a1 * bv.z; acc[1][3] += a1 * bv.w;
            acc[2][0] += a2 * bv.x; acc[2][1] += a2 * bv.y; acc[2][2] += a2 * bv.z; acc[2][3] += a2 * bv.w;
            acc[3][0] += a3 * bv.x; acc[3][1] += a3 * bv.y; acc[3][2] += a3 * bv.z; acc[3][3] += a3 * bv.w;
        }
        __syncthreads();
    }
    #pragma unroll
    for (int ii = 0; ii < 4; ii++) {
        int o = o0 + ty * 4 + ii;
        float bi = bias[o];
        size_t off = (size_t)(b * NC + o) * NHW + n0 + tx * 4;
        float4 res = *(const float4*)&x[off];
        float4 rv = make_float4(acc[ii][0] + bi + res.x, acc[ii][1] + bi + res.y,
                                acc[ii][2] + bi + res.z, acc[ii][3] + bi + res.w);
        *(float4*)&out[off] = rv;
    }
}

// ---------------------------------------------------------------------------
extern "C" void kernel_launch(void* const* d_in, const int* in_sizes, int n_in,
                              void* d_out, int out_size) {
    const float* x      = (const float*)d_in[0];
    const float* gn_w   = (const float*)d_in[1];
    const float* gn_b   = (const float*)d_in[2];
    const float* qkv_w  = (const float*)d_in[3];
    const float* qkv_b  = (const float*)d_in[4];
    const float* proj_w = (const float*)d_in[5];
    const float* proj_b = (const float*)d_in[6];
    float* out = (float*)d_out;

    cudaFuncSetAttribute(attn_kernel, cudaFuncAttributeMaxDynamicSharedMemorySize,
                         ATTN_SMEM);

    gn_kernel<<<NB * NHEADS, 512>>>(x, gn_w, gn_b);
    qkv_gemm<<<dim3(NHW / 64, QC / 64, NB), 256>>>(qkv_w, qkv_b);
    attn_kernel<<<dim3(NHW / 64, NHEADS, NB), 256, ATTN_SMEM>>>();
    proj_gemm<<<dim3(NHW / 64, NC / 64, NB), 256>>>(proj_w, proj_b, x, out);
}

// round 4
// speedup vs baseline: 1.4263x; 1.4263x over previous
#include <cuda_runtime.h>
#include <cuda_bf16.h>
#include <cstdint>
#include <math.h>

// Problem constants
#define NB     16
#define NC     512
#define NHW    1024
#define NHEADS 8
#define ND     64
#define QC     1536     // 3*NC
#define GN_EPS 1e-5f

// ===========================================================================
// Warp-level MMA helpers (sm_80+ paths — legal on base sm_100)
// ===========================================================================
__device__ __forceinline__ uint32_t smem_to_u32(const void* p) {
    uint32_t a;
    asm("{ .reg .u64 t; cvta.to.shared.u64 t, %1; cvt.u32.u64 %0, t; }" : "=r"(a) : "l"(p));
    return a;
}
__device__ __forceinline__ void ldsm4(uint32_t* r, uint32_t addr) {
    asm volatile("ldmatrix.sync.aligned.m8n8.x4.shared.b16 {%0,%1,%2,%3}, [%4];"
                 : "=r"(r[0]), "=r"(r[1]), "=r"(r[2]), "=r"(r[3]) : "r"(addr));
}
__device__ __forceinline__ void mma_bf16(float* d, const uint32_t* a, const uint32_t* b) {
    asm volatile("mma.sync.aligned.m16n8k16.row.col.f32.bf16.bf16.f32 "
                 "{%0,%1,%2,%3}, {%4,%5,%6,%7}, {%8,%9}, {%0,%1,%2,%3};"
                 : "+f"(d[0]), "+f"(d[1]), "+f"(d[2]), "+f"(d[3])
                 : "r"(a[0]), "r"(a[1]), "r"(a[2]), "r"(a[3]), "r"(b[0]), "r"(b[1]));
}
__device__ __forceinline__ void cp_async16(uint32_t daddr, const void* g) {
    asm volatile("cp.async.cg.shared.global [%0], [%1], 16;" :: "r"(daddr), "l"(g));
}
#define CP_COMMIT() asm volatile("cp.async.commit_group;" ::: "memory")
#define CP_WAIT(N)  asm volatile("cp.async.wait_group %0;" :: "n"(N) : "memory")

// ===========================================================================
// Scratch (device globals — no allocation allowed)
// ===========================================================================
__device__ float g_xn [NB * NC * NHW];               // groupnorm out [b][c][n]
__device__ float g_qkv[NB * QC * NHW];               // qkv fp32 [b][o][n]
__device__ float g_ao [NB * NC * NHW];               // attn out [b][c][n]
__device__ __nv_bfloat16 g_xh [NB * NHW * NC];       // xn transposed hi [b][n][c]
__device__ __nv_bfloat16 g_xl [NB * NHW * NC];       // xn transposed lo
__device__ __nv_bfloat16 g_aoh[NB * NHW * NC];       // ao transposed hi
__device__ __nv_bfloat16 g_aol[NB * NHW * NC];       // ao transposed lo
__device__ __nv_bfloat16 g_qwh[QC * NC];             // qkv_w hi  [o][c]
__device__ __nv_bfloat16 g_qwl[QC * NC];
__device__ __nv_bfloat16 g_pwh[NC * NC];             // proj_w hi
__device__ __nv_bfloat16 g_pwl[NC * NC];

// ---------------------------------------------------------------------------
// Kernel 1: GroupNorm
// ---------------------------------------------------------------------------
__global__ __launch_bounds__(512) void gn_kernel(const float* __restrict__ x,
                                                 const float* __restrict__ gw,
                                                 const float* __restrict__ gb) {
    int bg = blockIdx.x;
    int b = bg >> 3, g = bg & 7;
    const float4* xp = (const float4*)(x + (size_t)(b * NC + g * 64) * NHW);
    float4* op = (float4*)(g_xn + (size_t)(b * NC + g * 64) * NHW);
    const int NE4 = 64 * NHW / 4;
    int tid = threadIdx.x;

    float s = 0.f, s2 = 0.f;
    for (int i = tid; i < NE4; i += 512) {
        float4 v = xp[i];
        s  += v.x + v.y + v.z + v.w;
        s2 += v.x * v.x + v.y * v.y + v.z * v.z + v.w * v.w;
    }
    __shared__ float rs[16], rs2[16];
    #pragma unroll
    for (int o = 16; o > 0; o >>= 1) {
        s  += __shfl_down_sync(0xFFFFFFFFu, s, o);
        s2 += __shfl_down_sync(0xFFFFFFFFu, s2, o);
    }
    int w = tid >> 5, l = tid & 31;
    if (l == 0) { rs[w] = s; rs2[w] = s2; }
    __syncthreads();
    __shared__ float sh_mean, sh_rstd;
    if (tid == 0) {
        float S = 0.f, S2 = 0.f;
        #pragma unroll
        for (int i = 0; i < 16; i++) { S += rs[i]; S2 += rs2[i]; }
        float mean = S * (1.f / 65536.f);
        float var  = S2 * (1.f / 65536.f) - mean * mean;
        sh_mean = mean;
        sh_rstd = rsqrtf(var + GN_EPS);
    }
    __syncthreads();
    float mean = sh_mean, rstd = sh_rstd;
    for (int i = tid; i < NE4; i += 512) {
        int c = g * 64 + (i >> 8);
        float sc = gw[c] * rstd;
        float bi = gb[c] - mean * sc;
        float4 v = xp[i];
        v.x = v.x * sc + bi; v.y = v.y * sc + bi;
        v.z = v.z * sc + bi; v.w = v.w * sc + bi;
        op[i] = v;
    }
}

// ---------------------------------------------------------------------------
// Convert weights fp32 -> bf16 hi/lo (same layout)
// ---------------------------------------------------------------------------
__global__ void convert_w(const float* __restrict__ src, __nv_bfloat16* __restrict__ dh,
                          __nv_bfloat16* __restrict__ dl, int n) {
    int i = blockIdx.x * 256 + threadIdx.x;
    if (i < n) {
        float v = src[i];
        __nv_bfloat16 h = __float2bfloat16(v);
        dh[i] = h;
        dl[i] = __float2bfloat16(v - __bfloat162float(h));
    }
}

// ---------------------------------------------------------------------------
// Transpose+convert: src fp32 [b][c][n] -> dh/dl bf16 [b][n][c]
// ---------------------------------------------------------------------------
__global__ __launch_bounds__(256) void convert_t(const float* __restrict__ src,
                                                 __nv_bfloat16* __restrict__ dh,
                                                 __nv_bfloat16* __restrict__ dl) {
    __shared__ float t[32][33];
    int tx = threadIdx.x, ty = threadIdx.y;
    int n0 = blockIdx.x * 32, c0 = blockIdx.y * 32, b = blockIdx.z;
    const float* s = src + ((size_t)b * NC + c0) * NHW + n0;
    #pragma unroll
    for (int i = 0; i < 4; i++)
        t[ty + 8 * i][tx] = s[(size_t)(ty + 8 * i) * NHW + tx];
    __syncthreads();
    size_t ob = ((size_t)b * NHW + n0) * NC + c0;
    #pragma unroll
    for (int i = 0; i < 4; i++) {
        float v = t[tx][ty + 8 * i];
        __nv_bfloat16 h = __float2bfloat16(v);
        size_t o = ob + (size_t)(ty + 8 * i) * NC + tx;
        dh[o] = h;
        dl[o] = __float2bfloat16(v - __bfloat162float(h));
    }
}

// ---------------------------------------------------------------------------
// mma.sync GEMM: out[b][o][n] = sum_c W[o][c]*X[b][n][c] (+bias, +residual)
// CTA tile 128(o) x 128(n); 8 warps in 2(m) x 4(n); warp tile 64x32.
// bf16x3 split: D = Ah*Bh + Ah*Bl + Al*Bh, fp32 accumulation.
// cp.async double-buffered k-chunks of 32. smem rows padded to 80B.
// ---------------------------------------------------------------------------
#define TILE_B   10240        // one 128x32 bf16 tile with 80B rows
#define STAGE_B  (4 * TILE_B) // Ah, Al, Bh, Bl
#define GEMM_SMEM (2 * STAGE_B)

__global__ __launch_bounds__(256) void gemm_mma(
        const __nv_bfloat16* __restrict__ Ah, const __nv_bfloat16* __restrict__ Al,
        const __nv_bfloat16* __restrict__ Bh, const __nv_bfloat16* __restrict__ Bl,
        const float* __restrict__ bias, const float* __restrict__ residual,
        float* __restrict__ out, int OC) {
    extern __shared__ char smem[];
    uint32_t smem_u = smem_to_u32(smem);
    int tid = threadIdx.x;
    int warp = tid >> 5, lane = tid & 31;
    int wm = warp & 1, wn = warp >> 1;          // 2 x 4 warp grid
    int n0 = blockIdx.x * 128;
    int o0 = blockIdx.y * 128;
    int b  = blockIdx.z;

    const __nv_bfloat16* a0 = Ah + (size_t)o0 * NC;
    const __nv_bfloat16* a1 = Al + (size_t)o0 * NC;
    const __nv_bfloat16* b0 = Bh + ((size_t)b * NHW + n0) * NC;
    const __nv_bfloat16* b1 = Bl + ((size_t)b * NHW + n0) * NC;
    const __nv_bfloat16* srcs[4] = {a0, a1, b0, b1};

    auto load_stage = [&](int chunk, int s) {
        int k0 = chunk * 32;
        uint32_t sbase = smem_u + s * STAGE_B;
        #pragma unroll
        for (int t = 0; t < 8; t++) {
            int tile = t >> 1;
            int c = ((t & 1) << 8) + tid;      // 0..511
            int row = c >> 2, ch = c & 3;
            uint32_t daddr = sbase + tile * TILE_B + row * 80 + ch * 16;
            cp_async16(daddr, srcs[tile] + (size_t)row * NC + k0 + ch * 8);
        }
        CP_COMMIT();
    };

    float acc[4][4][4] = {};
    // ldmatrix lane offsets (bytes)
    uint32_t aLane = (uint32_t)((lane & 15) * 80 + (lane >> 4) * 16);
    uint32_t bLane = (uint32_t)(((lane & 7) + ((lane >> 4) << 3)) * 80 + ((lane >> 3) & 1) * 16);

    load_stage(0, 0);
    #pragma unroll 1
    for (int c = 0; c < 16; c++) {
        if (c + 1 < 16) load_stage(c + 1, (c + 1) & 1);
        if (c + 1 < 16) { CP_WAIT(1); } else { CP_WAIT(0); }
        __syncthreads();

        uint32_t sbase = smem_u + (c & 1) * STAGE_B;
        uint32_t offAh = sbase            + (wm * 64) * 80 + aLane;
        uint32_t offAl = sbase + TILE_B   + (wm * 64) * 80 + aLane;
        uint32_t offBh = sbase + 2*TILE_B + (wn * 32) * 80 + bLane;
        uint32_t offBl = sbase + 3*TILE_B + (wn * 32) * 80 + bLane;

        #pragma unroll
        for (int ks = 0; ks < 2; ks++) {
            uint32_t ko = ks * 32;   // 16 halfs = 32 bytes
            uint32_t af[4][4], bh[2][4], bl[2][4];
            #pragma unroll
            for (int i = 0; i < 4; i++) ldsm4(af[i], offAh + i * 16 * 80 + ko);
            #pragma unroll
            for (int g = 0; g < 2; g++) ldsm4(bh[g], offBh + g * 16 * 80 + ko);
            #pragma unroll
            for (int g = 0; g < 2; g++) ldsm4(bl[g], offBl + g * 16 * 80 + ko);
            // pass 1: Ah*Bh
            #pragma unroll
            for (int i = 0; i < 4; i++)
                #pragma unroll
                for (int j = 0; j < 4; j++)
                    mma_bf16(acc[i][j], af[i], &bh[j >> 1][(j & 1) * 2]);
            // pass 2: Ah*Bl
            #pragma unroll
            for (int i = 0; i < 4; i++)
                #pragma unroll
                for (int j = 0; j < 4; j++)
                    mma_bf16(acc[i][j], af[i], &bl[j >> 1][(j & 1) * 2]);
            // pass 3: Al*Bh (reuse af regs)
            #pragma unroll
            for (int i = 0; i < 4; i++) ldsm4(af[i], offAl + i * 16 * 80 + ko);
            #pragma unroll
            for (int i = 0; i < 4; i++)
                #pragma unroll
                for (int j = 0; j < 4; j++)
                    mma_bf16(acc[i][j], af[i], &bh[j >> 1][(j & 1) * 2]);
        }
        __syncthreads();
    }

    // Epilogue: acc[i][j] frag -> out rows o0+wm*64+i*16+{r, r+8}, cols n0+wn*32+j*8+c0
    int r0 = lane >> 2, c0 = (lane & 3) * 2;
    #pragma unroll
    for (int i = 0; i < 4; i++) {
        #pragma unroll
        for (int half = 0; half < 2; half++) {
            int o = o0 + wm * 64 + i * 16 + r0 + half * 8;
            float bi = bias[o];
            size_t rowb = ((size_t)b * OC + o) * NHW + n0 + wn * 32 + c0;
            #pragma unroll
            for (int j = 0; j < 4; j++) {
                float v0 = acc[i][j][half * 2]     + bi;
                float v1 = acc[i][j][half * 2 + 1] + bi;
                size_t off = rowb + j * 8;
                if (residual) {
                    float2 rr = *(const float2*)&residual[off];
                    v0 += rr.x; v1 += rr.y;
                }
                *(float2*)&out[off] = make_float2(v0, v1);
            }
        }
    }
}

// ---------------------------------------------------------------------------
// Kernel 3: fused flash attention (unchanged from R1)
// ---------------------------------------------------------------------------
#define SROW 68
#define ATTN_SMEM ((4 * 64 * SROW + 256 + 3 * 64) * 4)

__global__ __launch_bounds__(256) void attn_kernel() {
    extern __shared__ float sm[];
    float* Qs   = sm;
    float* Ks   = Qs + 64 * SROW;
    float* Vs   = Ks + 64 * SROW;
    float* Ss   = Vs + 64 * SROW;
    float* red  = Ss + 64 * SROW;
    float* m_s  = red + 256;
    float* l_s  = m_s + 64;
    float* al_s = l_s + 64;

    int tid = threadIdx.x;
    int tx = tid & 15, ty = tid >> 4;
    int qt = blockIdx.x, h = blockIdx.y, b = blockIdx.z;

    const float* qb = g_qkv + ((size_t)b * QC + h * ND) * NHW + qt * 64;
    const float* kb = g_qkv + ((size_t)b * QC + NC + h * ND) * NHW;
    const float* vb = g_qkv + ((size_t)b * QC + 2 * NC + h * ND) * NHW;

    #pragma unroll
    for (int it = 0; it < 4; it++) {
        int i = tid + it * 256;
        int dd = i >> 4, c4 = i & 15;
        float4 v = *(const float4*)&qb[(size_t)dd * NHW + c4 * 4];
        v.x *= 0.125f; v.y *= 0.125f; v.z *= 0.125f; v.w *= 0.125f;
        *(float4*)&Qs[dd * SROW + c4 * 4] = v;
    }
    if (tid < 64) { m_s[tid] = -1e30f; l_s[tid] = 0.f; }

    float o[4][4] = {};
    int r = tid & 63, seg = tid >> 6;

    for (int mt = 0; mt < 16; mt++) {
        __syncthreads();
        const float* kp = kb + mt * 64;
        const float* vp = vb + mt * 64;
        #pragma unroll
        for (int it = 0; it < 4; it++) {
            int i = tid + it * 256;
            int dd = i >> 4, c4 = i & 15;
            *(float4*)&Ks[dd * SROW + c4 * 4] = *(const float4*)&kp[(size_t)dd * NHW + c4 * 4];
            *(float4*)&Vs[dd * SROW + c4 * 4] = *(const float4*)&vp[(size_t)dd * NHW + c4 * 4];
        }
        __syncthreads();

        float s[4][4] = {};
        #pragma unroll 8
        for (int dd = 0; dd < 64; dd++) {
            float4 qa = *(const float4*)&Qs[dd * SROW + ty * 4];
            float4 kv = *(const float4*)&Ks[dd * SROW + tx * 4];
            s[0][0] += qa.x * kv.x; s[0][1] += qa.x * kv.y; s[0][2] += qa.x * kv.z; s[0][3] += qa.x * kv.w;
            s[1][0] += qa.y * kv.x; s[1][1] += qa.y * kv.y; s[1][2] += qa.y * kv.z; s[1][3] += qa.y * kv.w;
            s[2][0] += qa.z * kv.x; s[2][1] += qa.z * kv.y; s[2][2] += qa.z * kv.z; s[2][3] += qa.z * kv.w;
            s[3][0] += qa.w * kv.x; s[3][1] += qa.w * kv.y; s[3][2] += qa.w * kv.z; s[3][3] += qa.w * kv.w;
        }
        #pragma unroll
        for (int ii = 0; ii < 4; ii++)
            *(float4*)&Ss[(ty * 4 + ii) * SROW + tx * 4] =
                make_float4(s[ii][0], s[ii][1], s[ii][2], s[ii][3]);
        __syncthreads();

        float pm = -1e30f;
        #pragma unroll
        for (int j = 0; j < 16; j++) pm = fmaxf(pm, Ss[r * SROW + seg * 16 + j]);
        red[seg * 64 + r] = pm;
        __syncthreads();
        if (tid < 64) {
            float tm = fmaxf(fmaxf(red[tid], red[64 + tid]),
                             fmaxf(red[128 + tid], red[192 + tid]));
            float nm = fmaxf(m_s[tid], tm);
            float al = __expf(m_s[tid] - nm);
            al_s[tid] = al;
            l_s[tid] *= al;
            m_s[tid] = nm;
        }
        __syncthreads();
        float mr = m_s[r];
        float ps = 0.f;
        #pragma unroll
        for (int j = 0; j < 16; j++) {
            float p = __expf(Ss[r * SROW + seg * 16 + j] - mr);
            Ss[r * SROW + seg * 16 + j] = p;
            ps += p;
        }
        red[seg * 64 + r] = ps;
        __syncthreads();
        if (tid < 64)
            l_s[tid] += red[tid] + red[64 + tid] + red[128 + tid] + red[192 + tid];

        #pragma unroll
        for (int jj = 0; jj < 4; jj++) {
            float al = al_s[jj * 16 + tx];
            o[0][jj] *= al; o[1][jj] *= al; o[2][jj] *= al; o[3][jj] *= al;
        }
        #pragma unroll 4
        for (int m4 = 0; m4 < 16; m4++) {
            float4 vv[4], pp[4];
            #pragma unroll
            for (int ii = 0; ii < 4; ii++)
                vv[ii] = *(const float4*)&Vs[(ty * 4 + ii) * SROW + m4 * 4];
            #pragma unroll
            for (int jj = 0; jj < 4; jj++)
                pp[jj] = *(const float4*)&Ss[(jj * 16 + tx) * SROW + m4 * 4];
            #pragma unroll
            for (int ii = 0; ii < 4; ii++)
                #pragma unroll
                for (int jj = 0; jj < 4; jj++)
                    o[ii][jj] += pp[jj].x * vv[ii].x + pp[jj].y * vv[ii].y +
                                 pp[jj].z * vv[ii].z + pp[jj].w * vv[ii].w;
        }
    }
    __syncthreads();

    float* op = g_ao + ((size_t)b * NC + h * ND) * NHW + qt * 64;
    #pragma unroll
    for (int jj = 0; jj < 4; jj++) {
        float linv = 1.f / l_s[jj * 16 + tx];
        #pragma unroll
        for (int ii = 0; ii < 4; ii++)
            op[(size_t)(ty * 4 + ii) * NHW + jj * 16 + tx] = o[ii][jj] * linv;
    }
}

// ---------------------------------------------------------------------------
extern "C" void kernel_launch(void* const* d_in, const int* in_sizes, int n_in,
                              void* d_out, int out_size) {
    const float* x      = (const float*)d_in[0];
    const float* gn_w   = (const float*)d_in[1];
    const float* gn_b   = (const float*)d_in[2];
    const float* qkv_w  = (const float*)d_in[3];
    const float* qkv_b  = (const float*)d_in[4];
    const float* proj_w = (const float*)d_in[5];
    const float* proj_b = (const float*)d_in[6];
    float* out = (float*)d_out;

    cudaFuncSetAttribute(attn_kernel, cudaFuncAttributeMaxDynamicSharedMemorySize, ATTN_SMEM);
    cudaFuncSetAttribute(gemm_mma, cudaFuncAttributeMaxDynamicSharedMemorySize, GEMM_SMEM);

    __nv_bfloat16 *qwh, *qwl, *pwh, *pwl, *xh, *xl, *aoh, *aol;
    cudaGetSymbolAddress((void**)&qwh, g_qwh);
    cudaGetSymbolAddress((void**)&qwl, g_qwl);
    cudaGetSymbolAddress((void**)&pwh, g_pwh);
    cudaGetSymbolAddress((void**)&pwl, g_pwl);
    cudaGetSymbolAddress((void**)&xh,  g_xh);
    cudaGetSymbolAddress((void**)&xl,  g_xl);
    cudaGetSymbolAddress((void**)&aoh, g_aoh);
    cudaGetSymbolAddress((void**)&aol, g_aol);
    float *xnp, *qkvp, *aop;
    cudaGetSymbolAddress((void**)&xnp, g_xn);
    cudaGetSymbolAddress((void**)&qkvp, g_qkv);
    cudaGetSymbolAddress((void**)&aop, g_ao);

    // 1. GroupNorm
    gn_kernel<<<NB * 8, 512>>>(x, gn_w, gn_b);
    // 2. Weight conversion (bf16 hi/lo)
    convert_w<<<(QC * NC + 255) / 256, 256>>>(qkv_w, qwh, qwl, QC * NC);
    convert_w<<<(NC * NC + 255) / 256, 256>>>(proj_w, pwh, pwl, NC * NC);
    // 3. Transpose+convert xn -> [b][n][c] bf16 hi/lo
    convert_t<<<dim3(NHW / 32, NC / 32, NB), dim3(32, 8)>>>(xnp, xh, xl);
    // 4. QKV GEMM (tensor cores via mma.sync)
    gemm_mma<<<dim3(NHW / 128, QC / 128, NB), 256, GEMM_SMEM>>>(
        qwh, qwl, xh, xl, qkv_b, nullptr, qkvp, QC);
    // 5. Attention
    attn_kernel<<<dim3(NHW / 64, NHEADS, NB), 256, ATTN_SMEM>>>();
    // 6. Transpose+convert ao
    convert_t<<<dim3(NHW / 32, NC / 32, NB), dim3(32, 8)>>>(aop, aoh, aol);
    // 7. Proj GEMM + bias + residual
    gemm_mma<<<dim3(NHW / 128, NC / 128, NB), 256, GEMM_SMEM>>>(
        pwh, pwl, aoh, aol, proj_b, x, out, NC);
}

// round 5
// speedup vs baseline: 2.6488x; 1.8572x over previous
#include <cuda_runtime.h>
#include <cuda_bf16.h>
#include <cstdint>
#include <math.h>

// Problem constants
#define NB     16
#define NC     512
#define NHW    1024
#define NHEADS 8
#define ND     64
#define QC     1536     // 3*NC
#define GN_EPS 1e-5f

// ===========================================================================
// Warp-level MMA helpers (sm_80+ paths — legal on base sm_100)
// ===========================================================================
__device__ __forceinline__ uint32_t smem_to_u32(const void* p) {
    uint32_t a;
    asm("{ .reg .u64 t; cvta.to.shared.u64 t, %1; cvt.u32.u64 %0, t; }" : "=r"(a) : "l"(p));
    return a;
}
__device__ __forceinline__ void ldsm4(uint32_t* r, uint32_t addr) {
    asm volatile("ldmatrix.sync.aligned.m8n8.x4.shared.b16 {%0,%1,%2,%3}, [%4];"
                 : "=r"(r[0]), "=r"(r[1]), "=r"(r[2]), "=r"(r[3]) : "r"(addr));
}
__device__ __forceinline__ void ldsm4t(uint32_t* r, uint32_t addr) {
    asm volatile("ldmatrix.sync.aligned.m8n8.x4.trans.shared.b16 {%0,%1,%2,%3}, [%4];"
                 : "=r"(r[0]), "=r"(r[1]), "=r"(r[2]), "=r"(r[3]) : "r"(addr));
}
__device__ __forceinline__ void mma_bf16(float* d, const uint32_t* a, const uint32_t* b) {
    asm volatile("mma.sync.aligned.m16n8k16.row.col.f32.bf16.bf16.f32 "
                 "{%0,%1,%2,%3}, {%4,%5,%6,%7}, {%8,%9}, {%0,%1,%2,%3};"
                 : "+f"(d[0]), "+f"(d[1]), "+f"(d[2]), "+f"(d[3])
                 : "r"(a[0]), "r"(a[1]), "r"(a[2]), "r"(a[3]), "r"(b[0]), "r"(b[1]));
}
__device__ __forceinline__ void mma4(float* d, uint32_t a0, uint32_t a1, uint32_t a2,
                                     uint32_t a3, uint32_t b0, uint32_t b1) {
    asm volatile("mma.sync.aligned.m16n8k16.row.col.f32.bf16.bf16.f32 "
                 "{%0,%1,%2,%3}, {%4,%5,%6,%7}, {%8,%9}, {%0,%1,%2,%3};"
                 : "+f"(d[0]), "+f"(d[1]), "+f"(d[2]), "+f"(d[3])
                 : "r"(a0), "r"(a1), "r"(a2), "r"(a3), "r"(b0), "r"(b1));
}
__device__ __forceinline__ void cp_async16(uint32_t daddr, const void* g) {
    asm volatile("cp.async.cg.shared.global [%0], [%1], 16;" :: "r"(daddr), "l"(g));
}
#define CP_COMMIT() asm volatile("cp.async.commit_group;" ::: "memory")
#define CP_WAIT(N)  asm volatile("cp.async.wait_group %0;" :: "n"(N) : "memory")

// pack two fp32 -> bf16x2 (lo first)
__device__ __forceinline__ uint32_t packbf(float lo, float hi) {
    uint32_t r;
    asm("cvt.rn.bf16x2.f32 %0, %1, %2;" : "=r"(r) : "f"(hi), "f"(lo));
    return r;
}

// ===========================================================================
// Scratch (device globals — no allocation allowed)
// ===========================================================================
__device__ float g_xn [NB * NC * NHW];               // groupnorm out [b][c][n]
__device__ float g_qkv[NB * QC * NHW];               // qkv fp32 [b][o][n]
__device__ __nv_bfloat16 g_xh [NB * NHW * NC];       // xn transposed hi [b][n][c]
__device__ __nv_bfloat16 g_xl [NB * NHW * NC];       // xn transposed lo
__device__ __nv_bfloat16 g_aoh[NB * NHW * NC];       // attn out hi [b][n][c]
__device__ __nv_bfloat16 g_aol[NB * NHW * NC];       // attn out lo
__device__ __nv_bfloat16 g_qkvh[NB * QC * NHW];      // qkv hi [b][o][n] (Q pre-scaled)
__device__ __nv_bfloat16 g_qkvl[NB * QC * NHW];      // qkv lo
__device__ __nv_bfloat16 g_qwh[QC * NC];             // qkv_w hi  [o][c]
__device__ __nv_bfloat16 g_qwl[QC * NC];
__device__ __nv_bfloat16 g_pwh[NC * NC];             // proj_w hi
__device__ __nv_bfloat16 g_pwl[NC * NC];

// ---------------------------------------------------------------------------
// Kernel 1: GroupNorm
// ---------------------------------------------------------------------------
__global__ __launch_bounds__(512) void gn_kernel(const float* __restrict__ x,
                                                 const float* __restrict__ gw,
                                                 const float* __restrict__ gb) {
    int bg = blockIdx.x;
    int b = bg >> 3, g = bg & 7;
    const float4* xp = (const float4*)(x + (size_t)(b * NC + g * 64) * NHW);
    float4* op = (float4*)(g_xn + (size_t)(b * NC + g * 64) * NHW);
    const int NE4 = 64 * NHW / 4;
    int tid = threadIdx.x;

    float s = 0.f, s2 = 0.f;
    for (int i = tid; i < NE4; i += 512) {
        float4 v = xp[i];
        s  += v.x + v.y + v.z + v.w;
        s2 += v.x * v.x + v.y * v.y + v.z * v.z + v.w * v.w;
    }
    __shared__ float rs[16], rs2[16];
    #pragma unroll
    for (int o = 16; o > 0; o >>= 1) {
        s  += __shfl_down_sync(0xFFFFFFFFu, s, o);
        s2 += __shfl_down_sync(0xFFFFFFFFu, s2, o);
    }
    int w = tid >> 5, l = tid & 31;
    if (l == 0) { rs[w] = s; rs2[w] = s2; }
    __syncthreads();
    __shared__ float sh_mean, sh_rstd;
    if (tid == 0) {
        float S = 0.f, S2 = 0.f;
        #pragma unroll
        for (int i = 0; i < 16; i++) { S += rs[i]; S2 += rs2[i]; }
        float mean = S * (1.f / 65536.f);
        float var  = S2 * (1.f / 65536.f) - mean * mean;
        sh_mean = mean;
        sh_rstd = rsqrtf(var + GN_EPS);
    }
    __syncthreads();
    float mean = sh_mean, rstd = sh_rstd;
    for (int i = tid; i < NE4; i += 512) {
        int c = g * 64 + (i >> 8);
        float sc = gw[c] * rstd;
        float bi = gb[c] - mean * sc;
        float4 v = xp[i];
        v.x = v.x * sc + bi; v.y = v.y * sc + bi;
        v.z = v.z * sc + bi; v.w = v.w * sc + bi;
        op[i] = v;
    }
}

// ---------------------------------------------------------------------------
// Convert weights fp32 -> bf16 hi/lo (same layout)
// ---------------------------------------------------------------------------
__global__ void convert_w(const float* __restrict__ src, __nv_bfloat16* __restrict__ dh,
                          __nv_bfloat16* __restrict__ dl, int n) {
    int i = blockIdx.x * 256 + threadIdx.x;
    if (i < n) {
        float v = src[i];
        __nv_bfloat16 h = __float2bfloat16(v);
        dh[i] = h;
        dl[i] = __float2bfloat16(v - __bfloat162float(h));
    }
}

// ---------------------------------------------------------------------------
// Transpose+convert: src fp32 [b][c][n] -> dh/dl bf16 [b][n][c]
// ---------------------------------------------------------------------------
__global__ __launch_bounds__(256) void convert_t(const float* __restrict__ src,
                                                 __nv_bfloat16* __restrict__ dh,
                                                 __nv_bfloat16* __restrict__ dl) {
    __shared__ float t[32][33];
    int tx = threadIdx.x, ty = threadIdx.y;
    int n0 = blockIdx.x * 32, c0 = blockIdx.y * 32, b = blockIdx.z;
    const float* s = src + ((size_t)b * NC + c0) * NHW + n0;
    #pragma unroll
    for (int i = 0; i < 4; i++)
        t[ty + 8 * i][tx] = s[(size_t)(ty + 8 * i) * NHW + tx];
    __syncthreads();
    size_t ob = ((size_t)b * NHW + n0) * NC + c0;
    #pragma unroll
    for (int i = 0; i < 4; i++) {
        float v = t[tx][ty + 8 * i];
        __nv_bfloat16 h = __float2bfloat16(v);
        size_t o = ob + (size_t)(ty + 8 * i) * NC + tx;
        dh[o] = h;
        dl[o] = __float2bfloat16(v - __bfloat162float(h));
    }
}

// ---------------------------------------------------------------------------
// Convert qkv fp32 [b][o][n] -> bf16 hi/lo same layout; Q rows scaled by 0.125
// ---------------------------------------------------------------------------
__global__ __launch_bounds__(256) void convert_qkv(const float* __restrict__ src,
                                                   __nv_bfloat16* __restrict__ dh,
                                                   __nv_bfloat16* __restrict__ dl) {
    size_t i = ((size_t)blockIdx.x * 256 + threadIdx.x) * 4;
    float4 v = *(const float4*)(src + i);
    int o = (int)((i >> 10) % QC);
    float sc = (o < NC) ? 0.125f : 1.0f;
    v.x *= sc; v.y *= sc; v.z *= sc; v.w *= sc;
    uint32_t h0 = packbf(v.x, v.y), h1 = packbf(v.z, v.w);
    float rx = v.x - __uint_as_float(h0 << 16);
    float ry = v.y - __uint_as_float(h0 & 0xFFFF0000u);
    float rz = v.z - __uint_as_float(h1 << 16);
    float rw = v.w - __uint_as_float(h1 & 0xFFFF0000u);
    uint32_t l0 = packbf(rx, ry), l1 = packbf(rz, rw);
    *(uint2*)(dh + i) = make_uint2(h0, h1);
    *(uint2*)(dl + i) = make_uint2(l0, l1);
}

// ---------------------------------------------------------------------------
// mma.sync GEMM: out[b][o][n] = sum_c W[o][c]*X[b][n][c] (+bias, +residual)
// (unchanged from R4 — passed with rel_err 7.4e-7)
// ---------------------------------------------------------------------------
#define TILE_B   10240
#define STAGE_B  (4 * TILE_B)
#define GEMM_SMEM (2 * STAGE_B)

__global__ __launch_bounds__(256) void gemm_mma(
        const __nv_bfloat16* __restrict__ Ah, const __nv_bfloat16* __restrict__ Al,
        const __nv_bfloat16* __restrict__ Bh, const __nv_bfloat16* __restrict__ Bl,
        const float* __restrict__ bias, const float* __restrict__ residual,
        float* __restrict__ out, int OC) {
    extern __shared__ char smem[];
    uint32_t smem_u = smem_to_u32(smem);
    int tid = threadIdx.x;
    int warp = tid >> 5, lane = tid & 31;
    int wm = warp & 1, wn = warp >> 1;
    int n0 = blockIdx.x * 128;
    int o0 = blockIdx.y * 128;
    int b  = blockIdx.z;

    const __nv_bfloat16* a0 = Ah + (size_t)o0 * NC;
    const __nv_bfloat16* a1 = Al + (size_t)o0 * NC;
    const __nv_bfloat16* b0 = Bh + ((size_t)b * NHW + n0) * NC;
    const __nv_bfloat16* b1 = Bl + ((size_t)b * NHW + n0) * NC;
    const __nv_bfloat16* srcs[4] = {a0, a1, b0, b1};

    auto load_stage = [&](int chunk, int s) {
        int k0 = chunk * 32;
        uint32_t sbase = smem_u + s * STAGE_B;
        #pragma unroll
        for (int t = 0; t < 8; t++) {
            int tile = t >> 1;
            int c = ((t & 1) << 8) + tid;
            int row = c >> 2, ch = c & 3;
            uint32_t daddr = sbase + tile * TILE_B + row * 80 + ch * 16;
            cp_async16(daddr, srcs[tile] + (size_t)row * NC + k0 + ch * 8);
        }
        CP_COMMIT();
    };

    float acc[4][4][4] = {};
    uint32_t aLane = (uint32_t)((lane & 15) * 80 + (lane >> 4) * 16);
    uint32_t bLane = (uint32_t)(((lane & 7) + ((lane >> 4) << 3)) * 80 + ((lane >> 3) & 1) * 16);

    load_stage(0, 0);
    #pragma unroll 1
    for (int c = 0; c < 16; c++) {
        if (c + 1 < 16) load_stage(c + 1, (c + 1) & 1);
        if (c + 1 < 16) { CP_WAIT(1); } else { CP_WAIT(0); }
        __syncthreads();

        uint32_t sbase = smem_u + (c & 1) * STAGE_B;
        uint32_t offAh = sbase            + (wm * 64) * 80 + aLane;
        uint32_t offAl = sbase + TILE_B   + (wm * 64) * 80 + aLane;
        uint32_t offBh = sbase + 2*TILE_B + (wn * 32) * 80 + bLane;
        uint32_t offBl = sbase + 3*TILE_B + (wn * 32) * 80 + bLane;

        #pragma unroll
        for (int ks = 0; ks < 2; ks++) {
            uint32_t ko = ks * 32;
            uint32_t af[4][4], bh[2][4], bl[2][4];
            #pragma unroll
            for (int i = 0; i < 4; i++) ldsm4(af[i], offAh + i * 16 * 80 + ko);
            #pragma unroll
            for (int g = 0; g < 2; g++) ldsm4(bh[g], offBh + g * 16 * 80 + ko);
            #pragma unroll
            for (int g = 0; g < 2; g++) ldsm4(bl[g], offBl + g * 16 * 80 + ko);
            #pragma unroll
            for (int i = 0; i < 4; i++)
                #pragma unroll
                for (int j = 0; j < 4; j++)
                    mma_bf16(acc[i][j], af[i], &bh[j >> 1][(j & 1) * 2]);
            #pragma unroll
            for (int i = 0; i < 4; i++)
                #pragma unroll
                for (int j = 0; j < 4; j++)
                    mma_bf16(acc[i][j], af[i], &bl[j >> 1][(j & 1) * 2]);
            #pragma unroll
            for (int i = 0; i < 4; i++) ldsm4(af[i], offAl + i * 16 * 80 + ko);
            #pragma unroll
            for (int i = 0; i < 4; i++)
                #pragma unroll
                for (int j = 0; j < 4; j++)
                    mma_bf16(acc[i][j], af[i], &bh[j >> 1][(j & 1) * 2]);
        }
        __syncthreads();
    }

    int r0 = lane >> 2, c0 = (lane & 3) * 2;
    #pragma unroll
    for (int i = 0; i < 4; i++) {
        #pragma unroll
        for (int half = 0; half < 2; half++) {
            int o = o0 + wm * 64 + i * 16 + r0 + half * 8;
            float bi = bias[o];
            size_t rowb = ((size_t)b * OC + o) * NHW + n0 + wn * 32 + c0;
            #pragma unroll
            for (int j = 0; j < 4; j++) {
                float v0 = acc[i][j][half * 2]     + bi;
                float v1 = acc[i][j][half * 2 + 1] + bi;
                size_t off = rowb + j * 8;
                if (residual) {
                    float2 rr = *(const float2*)&residual[off];
                    v0 += rr.x; v1 += rr.y;
                }
                *(float2*)&out[off] = make_float2(v0, v1);
            }
        }
    }
}

// ---------------------------------------------------------------------------
// Kernel 3: flash attention via mma.sync, bf16x3 split everywhere.
// Block: 128 q (one (b,h) slice), loop over 16 key tiles of 64.
// Warp w owns q rows [w*16, w*16+16). S acc and O acc live in registers.
// Smem: Qh/Ql [64 dd][136 q], stages: Kh/Kl/Vh/Vl [64 dd][72 k] double-buffered.
// Epilogue writes O directly as bf16 hi/lo in [b][n][c] layout.
// ---------------------------------------------------------------------------
#define QSTR 136
#define KSTR 72
#define OSTR 132
#define Q_BYTES   17408          // 64*136*2
#define KV_TILE_B 9216           // 64*72*2
#define STAGE0_OFF (2 * Q_BYTES) // 34816
#define KV_STAGE_B (4 * KV_TILE_B)
#define ATTN_SMEM (STAGE0_OFF + 2 * KV_STAGE_B)   // 108544

__global__ __launch_bounds__(256, 2) void attn_mma() {
    extern __shared__ char smem[];
    uint32_t smem_u = smem_to_u32(smem);
    int tid  = threadIdx.x;
    int warp = tid >> 5, lane = tid & 31;
    int wbase = warp * 16;                 // q-row base within tile
    int qt = blockIdx.x, h = blockIdx.y, b = blockIdx.z;

    // global slices [dd][n]
    const __nv_bfloat16* gq_h = g_qkvh + ((size_t)b * QC + h * ND) * NHW;
    const __nv_bfloat16* gq_l = g_qkvl + ((size_t)b * QC + h * ND) * NHW;
    const __nv_bfloat16* gk_h = g_qkvh + ((size_t)b * QC + NC + h * ND) * NHW;
    const __nv_bfloat16* gk_l = g_qkvl + ((size_t)b * QC + NC + h * ND) * NHW;
    const __nv_bfloat16* gv_h = g_qkvh + ((size_t)b * QC + 2 * NC + h * ND) * NHW;
    const __nv_bfloat16* gv_l = g_qkvl + ((size_t)b * QC + 2 * NC + h * ND) * NHW;
    const __nv_bfloat16* kvsrc[4] = {gk_h, gk_l, gv_h, gv_l};

    // ldmatrix lane offsets (shared pattern for Q/K/V fragment loads)
    int rowoff = ((lane >> 4) << 3) + (lane & 7);
    int coloff = ((lane >> 3) & 1) * 8;

    auto load_stage = [&](int kt, int s) {
        uint32_t sb = smem_u + STAGE0_OFF + s * KV_STAGE_B;
        #pragma unroll
        for (int k = 0; k < 8; k++) {
            int c = tid + k * 256;
            int tile = c >> 9, row = (c >> 3) & 63, ch = c & 7;
            cp_async16(sb + tile * KV_TILE_B + row * (KSTR * 2) + ch * 16,
                       kvsrc[tile] + (size_t)row * NHW + kt * 64 + ch * 8);
        }
        CP_COMMIT();
    };

    // preload Q tiles + stage 0 (one cp.async group)
    {
        #pragma unroll
        for (int k = 0; k < 8; k++) {
            int c = tid + k * 256;
            int tile = c >> 10, row = (c >> 4) & 63, ch = c & 15;
            const __nv_bfloat16* src = tile ? gq_l : gq_h;
            cp_async16(smem_u + tile * Q_BYTES + row * (QSTR * 2) + ch * 16,
                       src + (size_t)row * NHW + qt * 128 + ch * 8);
        }
    }
    load_stage(0, 0);

    float m0 = -1e30f, m1 = -1e30f, l0 = 0.f, l1 = 0.f;
    float oacc[8][4] = {};

    // Q fragment base addresses (col = wbase + coloff)
    uint32_t qAddrH = smem_u + (uint32_t)(rowoff * (QSTR * 2) + (wbase + coloff) * 2);
    uint32_t qAddrL = qAddrH + Q_BYTES;

    #pragma unroll 1
    for (int kt = 0; kt < 16; kt++) {
        CP_WAIT(0);
        __syncthreads();
        if (kt < 15) load_stage(kt + 1, (kt + 1) & 1);

        uint32_t sb = smem_u + STAGE0_OFF + (kt & 1) * KV_STAGE_B;
        // --- S = Q K^T (bf16x3) ---
        float sacc[8][4] = {};
        #pragma unroll
        for (int kc = 0; kc < 4; kc++) {
            uint32_t qh[4], ql[4];
            ldsm4t(qh, qAddrH + kc * 16 * (QSTR * 2));
            ldsm4t(ql, qAddrL + kc * 16 * (QSTR * 2));
            uint32_t kBase = sb + (uint32_t)((kc * 16 + rowoff) * (KSTR * 2) + coloff * 2);
            #pragma unroll
            for (int ko2 = 0; ko2 < 4; ko2++) {
                uint32_t kh[4], kl[4];
                ldsm4t(kh, kBase + ko2 * 32);                 // 16 k cols * 2B
                ldsm4t(kl, kBase + KV_TILE_B + ko2 * 32);
                // regs: [0]=oct(2ko2) b0, [1]=oct(2ko2+1) b0, [2]=oct b1, [3]=oct+1 b1
                mma4(sacc[2*ko2],   qh[0],qh[1],qh[2],qh[3], kh[0], kh[2]);
                mma4(sacc[2*ko2+1], qh[0],qh[1],qh[2],qh[3], kh[1], kh[3]);
                mma4(sacc[2*ko2],   qh[0],qh[1],qh[2],qh[3], kl[0], kl[2]);
                mma4(sacc[2*ko2+1], qh[0],qh[1],qh[2],qh[3], kl[1], kl[3]);
                mma4(sacc[2*ko2],   ql[0],ql[1],ql[2],ql[3], kh[0], kh[2]);
                mma4(sacc[2*ko2+1], ql[0],ql[1],ql[2],ql[3], kh[1], kh[3]);
            }
        }

        // --- online softmax (rows r0 = wbase+lane>>2, r1 = +8) ---
        float tm0 = -1e30f, tm1 = -1e30f;
        #pragma unroll
        for (int j = 0; j < 8; j++) {
            tm0 = fmaxf(tm0, fmaxf(sacc[j][0], sacc[j][1]));
            tm1 = fmaxf(tm1, fmaxf(sacc[j][2], sacc[j][3]));
        }
        tm0 = fmaxf(tm0, __shfl_xor_sync(0xFFFFFFFFu, tm0, 1));
        tm0 = fmaxf(tm0, __shfl_xor_sync(0xFFFFFFFFu, tm0, 2));
        tm1 = fmaxf(tm1, __shfl_xor_sync(0xFFFFFFFFu, tm1, 1));
        tm1 = fmaxf(tm1, __shfl_xor_sync(0xFFFFFFFFu, tm1, 2));
        float nm0 = fmaxf(m0, tm0), nm1 = fmaxf(m1, tm1);
        float al0 = __expf(m0 - nm0), al1 = __expf(m1 - nm1);
        m0 = nm0; m1 = nm1;
        float sum0 = 0.f, sum1 = 0.f;
        #pragma unroll
        for (int j = 0; j < 8; j++) {
            sacc[j][0] = __expf(sacc[j][0] - m0); sum0 += sacc[j][0];
            sacc[j][1] = __expf(sacc[j][1] - m0); sum0 += sacc[j][1];
            sacc[j][2] = __expf(sacc[j][2] - m1); sum1 += sacc[j][2];
            sacc[j][3] = __expf(sacc[j][3] - m1); sum1 += sacc[j][3];
        }
        sum0 += __shfl_xor_sync(0xFFFFFFFFu, sum0, 1);
        sum0 += __shfl_xor_sync(0xFFFFFFFFu, sum0, 2);
        sum1 += __shfl_xor_sync(0xFFFFFFFFu, sum1, 1);
        sum1 += __shfl_xor_sync(0xFFFFFFFFu, sum1, 2);
        l0 = l0 * al0 + sum0;
        l1 = l1 * al1 + sum1;
        #pragma unroll
        for (int d = 0; d < 8; d++) {
            oacc[d][0] *= al0; oacc[d][1] *= al0;
            oacc[d][2] *= al1; oacc[d][3] *= al1;
        }

        // --- O += P V^T (bf16x3, P frags built from sacc in registers) ---
        uint32_t vB = sb + 2 * KV_TILE_B;
        #pragma unroll
        for (int kc2 = 0; kc2 < 4; kc2++) {
            int j0 = 2 * kc2, j1 = j0 + 1;
            // Ph frags
            uint32_t pa0 = packbf(sacc[j0][0], sacc[j0][1]);
            uint32_t pa1 = packbf(sacc[j0][2], sacc[j0][3]);
            uint32_t pa2 = packbf(sacc[j1][0], sacc[j1][1]);
            uint32_t pa3 = packbf(sacc[j1][2], sacc[j1][3]);
            // Pl frags (residuals)
            uint32_t pl0 = packbf(sacc[j0][0] - __uint_as_float(pa0 << 16),
                                  sacc[j0][1] - __uint_as_float(pa0 & 0xFFFF0000u));
            uint32_t pl1 = packbf(sacc[j0][2] - __uint_as_float(pa1 << 16),
                                  sacc[j0][3] - __uint_as_float(pa1 & 0xFFFF0000u));
            uint32_t pl2 = packbf(sacc[j1][0] - __uint_as_float(pa2 << 16),
                                  sacc[j1][1] - __uint_as_float(pa2 & 0xFFFF0000u));
            uint32_t pl3 = packbf(sacc[j1][2] - __uint_as_float(pa3 << 16),
                                  sacc[j1][3] - __uint_as_float(pa3 & 0xFFFF0000u));
            uint32_t vCol = (uint32_t)((kc2 * 16 + coloff) * 2);
            #pragma unroll
            for (int do2 = 0; do2 < 4; do2++) {
                uint32_t vh[4], vl[4];
                uint32_t vRow = (uint32_t)((do2 * 16 + rowoff) * (KSTR * 2));
                ldsm4(vh, vB + vRow + vCol);
                ldsm4(vl, vB + KV_TILE_B + vRow + vCol);
                // regs: [0]=oct(2do2) b0, [1]=oct b1, [2]=oct+1 b0, [3]=oct+1 b1
                mma4(oacc[2*do2],   pa0,pa1,pa2,pa3, vh[0], vh[1]);
                mma4(oacc[2*do2+1], pa0,pa1,pa2,pa3, vh[2], vh[3]);
                mma4(oacc[2*do2],   pl0,pl1,pl2,pl3, vh[0], vh[1]);
                mma4(oacc[2*do2+1], pl0,pl1,pl2,pl3, vh[2], vh[3]);
                mma4(oacc[2*do2],   pa0,pa1,pa2,pa3, vl[0], vl[1]);
                mma4(oacc[2*do2+1], pa0,pa1,pa2,pa3, vl[2], vl[3]);
            }
        }
    }

    // --- epilogue: stage O (normalized) into smem [64 dd][132 q] fp32 ---
    float* Os = (float*)(smem + STAGE0_OFF);
    float linv0 = 1.f / l0, linv1 = 1.f / l1;
    int r0q = wbase + (lane >> 2);
    int ddc = (lane & 3) * 2;
    #pragma unroll
    for (int d = 0; d < 8; d++) {
        Os[(d * 8 + ddc)     * OSTR + r0q]     = oacc[d][0] * linv0;
        Os[(d * 8 + ddc + 1) * OSTR + r0q]     = oacc[d][1] * linv0;
        Os[(d * 8 + ddc)     * OSTR + r0q + 8] = oacc[d][2] * linv1;
        Os[(d * 8 + ddc + 1) * OSTR + r0q + 8] = oacc[d][3] * linv1;
    }
    __syncthreads();

    // coop write: bf16 hi/lo to [b][n][c] (n = qt*128+q, c = h*64+dd)
    {
        int q = tid >> 1;
        int ddb = (tid & 1) * 32;
        uint32_t hb[16], lb[16];
        #pragma unroll
        for (int d = 0; d < 32; d += 2) {
            float f0 = Os[(ddb + d)     * OSTR + q];
            float f1 = Os[(ddb + d + 1) * OSTR + q];
            uint32_t hp = packbf(f0, f1);
            hb[d >> 1] = hp;
            lb[d >> 1] = packbf(f0 - __uint_as_float(hp << 16),
                                f1 - __uint_as_float(hp & 0xFFFF0000u));
        }
        size_t base = ((size_t)b * NHW + qt * 128 + q) * NC + h * 64 + ddb;
        #pragma unroll
        for (int u = 0; u < 4; u++) {
            *(uint4*)(g_aoh + base + u * 8) = *(uint4*)&hb[u * 4];
            *(uint4*)(g_aol + base + u * 8) = *(uint4*)&lb[u * 4];
        }
    }
}

// ---------------------------------------------------------------------------
extern "C" void kernel_launch(void* const* d_in, const int* in_sizes, int n_in,
                              void* d_out, int out_size) {
    const float* x      = (const float*)d_in[0];
    const float* gn_w   = (const float*)d_in[1];
    const float* gn_b   = (const float*)d_in[2];
    const float* qkv_w  = (const float*)d_in[3];
    const float* qkv_b  = (const float*)d_in[4];
    const float* proj_w = (const float*)d_in[5];
    const float* proj_b = (const float*)d_in[6];
    float* out = (float*)d_out;

    cudaFuncSetAttribute(gemm_mma, cudaFuncAttributeMaxDynamicSharedMemorySize, GEMM_SMEM);
    cudaFuncSetAttribute(attn_mma, cudaFuncAttributeMaxDynamicSharedMemorySize, ATTN_SMEM);

    __nv_bfloat16 *qwh, *qwl, *pwh, *pwl, *xh, *xl, *aoh, *aol, *qkvh, *qkvl;
    cudaGetSymbolAddress((void**)&qwh, g_qwh);
    cudaGetSymbolAddress((void**)&qwl, g_qwl);
    cudaGetSymbolAddress((void**)&pwh, g_pwh);
    cudaGetSymbolAddress((void**)&pwl, g_pwl);
    cudaGetSymbolAddress((void**)&xh,  g_xh);
    cudaGetSymbolAddress((void**)&xl,  g_xl);
    cudaGetSymbolAddress((void**)&aoh, g_aoh);
    cudaGetSymbolAddress((void**)&aol, g_aol);
    cudaGetSymbolAddress((void**)&qkvh, g_qkvh);
    cudaGetSymbolAddress((void**)&qkvl, g_qkvl);
    float *xnp, *qkvp;
    cudaGetSymbolAddress((void**)&xnp, g_xn);
    cudaGetSymbolAddress((void**)&qkvp, g_qkv);

    // 1. GroupNorm
    gn_kernel<<<NB * 8, 512>>>(x, gn_w, gn_b);
    // 2. Weight conversion (bf16 hi/lo)
    convert_w<<<(QC * NC + 255) / 256, 256>>>(qkv_w, qwh, qwl, QC * NC);
    convert_w<<<(NC * NC + 255) / 256, 256>>>(proj_w, pwh, pwl, NC * NC);
    // 3. Transpose+convert xn -> [b][n][c] bf16 hi/lo
    convert_t<<<dim3(NHW / 32, NC / 32, NB), dim3(32, 8)>>>(xnp, xh, xl);
    // 4. QKV GEMM (mma.sync)
    gemm_mma<<<dim3(NHW / 128, QC / 128, NB), 256, GEMM_SMEM>>>(
        qwh, qwl, xh, xl, qkv_b, nullptr, qkvp, QC);
    // 5. Convert qkv -> bf16 hi/lo (Q pre-scaled by 1/8)
    convert_qkv<<<(NB * QC * NHW / 4 + 255) / 256, 256>>>(qkvp, qkvh, qkvl);
    // 6. Flash attention (mma.sync), writes g_aoh/g_aol in [b][n][c]
    attn_mma<<<dim3(NHW / 128, NHEADS, NB), 256, ATTN_SMEM>>>();
    // 7. Proj GEMM + bias + residual
    gemm_mma<<<dim3(NHW / 128, NC / 128, NB), 256, GEMM_SMEM>>>(
        pwh, pwl, aoh, aol, proj_b, x, out, NC);
}

// round 6
// speedup vs baseline: 2.7388x; 1.0340x over previous
#include <cuda_runtime.h>
#include <cuda_bf16.h>
#include <cstdint>
#include <math.h>

// Problem constants
#define NB     16
#define NC     512
#define NHW    1024
#define NHEADS 8
#define ND     64
#define QC     1536     // 3*NC
#define GN_EPS 1e-5f

// ===========================================================================
// Warp-level MMA helpers (sm_80+ paths — legal on base sm_100)
// ===========================================================================
__device__ __forceinline__ uint32_t smem_to_u32(const void* p) {
    uint32_t a;
    asm("{ .reg .u64 t; cvta.to.shared.u64 t, %1; cvt.u32.u64 %0, t; }" : "=r"(a) : "l"(p));
    return a;
}
__device__ __forceinline__ void ldsm4(uint32_t* r, uint32_t addr) {
    asm volatile("ldmatrix.sync.aligned.m8n8.x4.shared.b16 {%0,%1,%2,%3}, [%4];"
                 : "=r"(r[0]), "=r"(r[1]), "=r"(r[2]), "=r"(r[3]) : "r"(addr));
}
__device__ __forceinline__ void ldsm4t(uint32_t* r, uint32_t addr) {
    asm volatile("ldmatrix.sync.aligned.m8n8.x4.trans.shared.b16 {%0,%1,%2,%3}, [%4];"
                 : "=r"(r[0]), "=r"(r[1]), "=r"(r[2]), "=r"(r[3]) : "r"(addr));
}
__device__ __forceinline__ void mma_bf16(float* d, const uint32_t* a, const uint32_t* b) {
    asm volatile("mma.sync.aligned.m16n8k16.row.col.f32.bf16.bf16.f32 "
                 "{%0,%1,%2,%3}, {%4,%5,%6,%7}, {%8,%9}, {%0,%1,%2,%3};"
                 : "+f"(d[0]), "+f"(d[1]), "+f"(d[2]), "+f"(d[3])
                 : "r"(a[0]), "r"(a[1]), "r"(a[2]), "r"(a[3]), "r"(b[0]), "r"(b[1]));
}
__device__ __forceinline__ void mma4(float* d, uint32_t a0, uint32_t a1, uint32_t a2,
                                     uint32_t a3, uint32_t b0, uint32_t b1) {
    asm volatile("mma.sync.aligned.m16n8k16.row.col.f32.bf16.bf16.f32 "
                 "{%0,%1,%2,%3}, {%4,%5,%6,%7}, {%8,%9}, {%0,%1,%2,%3};"
                 : "+f"(d[0]), "+f"(d[1]), "+f"(d[2]), "+f"(d[3])
                 : "r"(a0), "r"(a1), "r"(a2), "r"(a3), "r"(b0), "r"(b1));
}
__device__ __forceinline__ void cp_async16(uint32_t daddr, const void* g) {
    asm volatile("cp.async.cg.shared.global [%0], [%1], 16;" :: "r"(daddr), "l"(g));
}
#define CP_COMMIT() asm volatile("cp.async.commit_group;" ::: "memory")
#define CP_WAIT(N)  asm volatile("cp.async.wait_group %0;" :: "n"(N) : "memory")

// pack two fp32 -> bf16x2 (lo first)
__device__ __forceinline__ uint32_t packbf(float lo, float hi) {
    uint32_t r;
    asm("cvt.rn.bf16x2.f32 %0, %1, %2;" : "=r"(r) : "f"(hi), "f"(lo));
    return r;
}

// ===========================================================================
// Scratch (device globals — no allocation allowed)
// ===========================================================================
__device__ float g_xn [NB * NC * NHW];               // groupnorm out [b][c][n]
__device__ __nv_bfloat16 g_xh [NB * NHW * NC];       // xn transposed hi [b][n][c]
__device__ __nv_bfloat16 g_xl [NB * NHW * NC];       // xn transposed lo
__device__ __nv_bfloat16 g_aoh[NB * NHW * NC];       // attn out hi [b][n][c]
__device__ __nv_bfloat16 g_aol[NB * NHW * NC];       // attn out lo
__device__ __nv_bfloat16 g_qkvh[NB * QC * NHW];      // qkv hi [b][o][n] (Q pre-scaled)
__device__ __nv_bfloat16 g_qkvl[NB * QC * NHW];      // qkv lo
__device__ __nv_bfloat16 g_qwh[QC * NC];             // qkv_w hi  [o][c]
__device__ __nv_bfloat16 g_qwl[QC * NC];
__device__ __nv_bfloat16 g_pwh[NC * NC];             // proj_w hi
__device__ __nv_bfloat16 g_pwl[NC * NC];

// ---------------------------------------------------------------------------
// Kernel 1: GroupNorm
// ---------------------------------------------------------------------------
__global__ __launch_bounds__(512) void gn_kernel(const float* __restrict__ x,
                                                 const float* __restrict__ gw,
                                                 const float* __restrict__ gb) {
    int bg = blockIdx.x;
    int b = bg >> 3, g = bg & 7;
    const float4* xp = (const float4*)(x + (size_t)(b * NC + g * 64) * NHW);
    float4* op = (float4*)(g_xn + (size_t)(b * NC + g * 64) * NHW);
    const int NE4 = 64 * NHW / 4;
    int tid = threadIdx.x;

    float s = 0.f, s2 = 0.f;
    for (int i = tid; i < NE4; i += 512) {
        float4 v = xp[i];
        s  += v.x + v.y + v.z + v.w;
        s2 += v.x * v.x + v.y * v.y + v.z * v.z + v.w * v.w;
    }
    __shared__ float rs[16], rs2[16];
    #pragma unroll
    for (int o = 16; o > 0; o >>= 1) {
        s  += __shfl_down_sync(0xFFFFFFFFu, s, o);
        s2 += __shfl_down_sync(0xFFFFFFFFu, s2, o);
    }
    int w = tid >> 5, l = tid & 31;
    if (l == 0) { rs[w] = s; rs2[w] = s2; }
    __syncthreads();
    __shared__ float sh_mean, sh_rstd;
    if (tid == 0) {
        float S = 0.f, S2 = 0.f;
        #pragma unroll
        for (int i = 0; i < 16; i++) { S += rs[i]; S2 += rs2[i]; }
        float mean = S * (1.f / 65536.f);
        float var  = S2 * (1.f / 65536.f) - mean * mean;
        sh_mean = mean;
        sh_rstd = rsqrtf(var + GN_EPS);
    }
    __syncthreads();
    float mean = sh_mean, rstd = sh_rstd;
    for (int i = tid; i < NE4; i += 512) {
        int c = g * 64 + (i >> 8);
        float sc = gw[c] * rstd;
        float bi = gb[c] - mean * sc;
        float4 v = xp[i];
        v.x = v.x * sc + bi; v.y = v.y * sc + bi;
        v.z = v.z * sc + bi; v.w = v.w * sc + bi;
        op[i] = v;
    }
}

// ---------------------------------------------------------------------------
// Convert weights fp32 -> bf16 hi/lo (same layout)
// ---------------------------------------------------------------------------
__global__ void convert_w(const float* __restrict__ src, __nv_bfloat16* __restrict__ dh,
                          __nv_bfloat16* __restrict__ dl, int n) {
    int i = blockIdx.x * 256 + threadIdx.x;
    if (i < n) {
        float v = src[i];
        __nv_bfloat16 h = __float2bfloat16(v);
        dh[i] = h;
        dl[i] = __float2bfloat16(v - __bfloat162float(h));
    }
}

// ---------------------------------------------------------------------------
// Transpose+convert: src fp32 [b][c][n] -> dh/dl bf16 [b][n][c]
// ---------------------------------------------------------------------------
__global__ __launch_bounds__(256) void convert_t(const float* __restrict__ src,
                                                 __nv_bfloat16* __restrict__ dh,
                                                 __nv_bfloat16* __restrict__ dl) {
    __shared__ float t[32][33];
    int tx = threadIdx.x, ty = threadIdx.y;
    int n0 = blockIdx.x * 32, c0 = blockIdx.y * 32, b = blockIdx.z;
    const float* s = src + ((size_t)b * NC + c0) * NHW + n0;
    #pragma unroll
    for (int i = 0; i < 4; i++)
        t[ty + 8 * i][tx] = s[(size_t)(ty + 8 * i) * NHW + tx];
    __syncthreads();
    size_t ob = ((size_t)b * NHW + n0) * NC + c0;
    #pragma unroll
    for (int i = 0; i < 4; i++) {
        float v = t[tx][ty + 8 * i];
        __nv_bfloat16 h = __float2bfloat16(v);
        size_t o = ob + (size_t)(ty + 8 * i) * NC + tx;
        dh[o] = h;
        dl[o] = __float2bfloat16(v - __bfloat162float(h));
    }
}

// ---------------------------------------------------------------------------
// QKV GEMM (new): CTA 128(o) x 256(n), 8 warps (2x4), warp tile 64x64.
// 3-stage cp.async pipeline (k-chunks of 32), bf16x3 split.
// Epilogue writes bf16 hi/lo in [b][o][n] with Q rows (o<NC) scaled by 0.125.
// ---------------------------------------------------------------------------
#define A2_TILE_B 10240              // 128 rows x 80B
#define B2_TILE_B 20480              // 256 rows x 80B
#define STAGE2_B  (2 * A2_TILE_B + 2 * B2_TILE_B)   // 61440
#define QKV_SMEM  (3 * STAGE2_B)                    // 184320

__global__ __launch_bounds__(256, 1) void qkv_gemm2(
        const __nv_bfloat16* __restrict__ Ah, const __nv_bfloat16* __restrict__ Al,
        const __nv_bfloat16* __restrict__ Bh, const __nv_bfloat16* __restrict__ Bl,
        const float* __restrict__ bias,
        __nv_bfloat16* __restrict__ outh, __nv_bfloat16* __restrict__ outl) {
    extern __shared__ char smem[];
    uint32_t smem_u = smem_to_u32(smem);
    int tid = threadIdx.x;
    int warp = tid >> 5, lane = tid & 31;
    int wm = warp & 1, wn = warp >> 1;     // 2(o) x 4(n)
    int n0 = blockIdx.x * 256;
    int o0 = blockIdx.y * 128;
    int b  = blockIdx.z;

    const __nv_bfloat16* a0 = Ah + (size_t)o0 * NC;
    const __nv_bfloat16* a1 = Al + (size_t)o0 * NC;
    const __nv_bfloat16* b0 = Bh + ((size_t)b * NHW + n0) * NC;
    const __nv_bfloat16* b1 = Bl + ((size_t)b * NHW + n0) * NC;

    auto load_stage = [&](int chunk, int s) {
        int k0 = chunk * 32;
        uint32_t sbase = smem_u + s * STAGE2_B;
        #pragma unroll
        for (int it = 0; it < 4; it++) {             // A hi/lo: 1024 cp
            int idx = it * 256 + tid;
            int tile = idx >> 9;
            int r = (idx >> 2) & 127;
            int ch = idx & 3;
            const __nv_bfloat16* src = tile ? a1 : a0;
            cp_async16(sbase + tile * A2_TILE_B + r * 80 + ch * 16,
                       src + (size_t)r * NC + k0 + ch * 8);
        }
        #pragma unroll
        for (int it = 0; it < 8; it++) {             // B hi/lo: 2048 cp
            int idx = it * 256 + tid;
            int tile = idx >> 10;
            int r = (idx >> 2) & 255;
            int ch = idx & 3;
            const __nv_bfloat16* src = tile ? b1 : b0;
            cp_async16(sbase + 2 * A2_TILE_B + tile * B2_TILE_B + r * 80 + ch * 16,
                       src + (size_t)r * NC + k0 + ch * 8);
        }
        CP_COMMIT();
    };

    float acc[4][8][4] = {};
    uint32_t aLane = (uint32_t)((lane & 15) * 80 + (lane >> 4) * 16);
    uint32_t bLane = (uint32_t)(((lane & 7) + ((lane >> 4) << 3)) * 80 + ((lane >> 3) & 1) * 16);

    load_stage(0, 0);
    load_stage(1, 1);
    #pragma unroll 1
    for (int c = 0; c < 16; c++) {
        if (c + 2 < 16) { load_stage(c + 2, (c + 2) % 3); CP_WAIT(2); }
        else if (c + 1 < 16) { CP_WAIT(1); }
        else { CP_WAIT(0); }
        __syncthreads();

        uint32_t sb = smem_u + (c % 3) * STAGE2_B;
        uint32_t offAh = sb                 + (wm * 64) * 80 + aLane;
        uint32_t offAl = sb + A2_TILE_B     + (wm * 64) * 80 + aLane;
        uint32_t offBh = sb + 2 * A2_TILE_B + (wn * 64) * 80 + bLane;
        uint32_t offBl = offBh + B2_TILE_B;

        #pragma unroll
        for (int ks = 0; ks < 2; ks++) {
            uint32_t ko = ks * 32;
            uint32_t af[4][4], bh[4][4], bl[4][4];
            #pragma unroll
            for (int i = 0; i < 4; i++) ldsm4(af[i], offAh + i * 16 * 80 + ko);
            #pragma unroll
            for (int g = 0; g < 4; g++) ldsm4(bh[g], offBh + g * 16 * 80 + ko);
            #pragma unroll
            for (int g = 0; g < 4; g++) ldsm4(bl[g], offBl + g * 16 * 80 + ko);
            #pragma unroll
            for (int i = 0; i < 4; i++)
                #pragma unroll
                for (int j = 0; j < 8; j++)
                    mma_bf16(acc[i][j], af[i], &bh[j >> 1][(j & 1) * 2]);
            #pragma unroll
            for (int i = 0; i < 4; i++)
                #pragma unroll
                for (int j = 0; j < 8; j++)
                    mma_bf16(acc[i][j], af[i], &bl[j >> 1][(j & 1) * 2]);
            #pragma unroll
            for (int i = 0; i < 4; i++) ldsm4(af[i], offAl + i * 16 * 80 + ko);
            #pragma unroll
            for (int i = 0; i < 4; i++)
                #pragma unroll
                for (int j = 0; j < 8; j++)
                    mma_bf16(acc[i][j], af[i], &bh[j >> 1][(j & 1) * 2]);
        }
        __syncthreads();
    }

    // Epilogue: bf16 hi/lo, Q rows scaled by 0.125
    int r0 = lane >> 2, c0 = (lane & 3) * 2;
    #pragma unroll
    for (int i = 0; i < 4; i++) {
        #pragma unroll
        for (int half = 0; half < 2; half++) {
            int o = o0 + wm * 64 + i * 16 + r0 + half * 8;
            float bi = bias[o];
            float sc = (o < NC) ? 0.125f : 1.0f;
            size_t rowb = ((size_t)b * QC + o) * NHW + n0 + wn * 64 + c0;
            #pragma unroll
            for (int j = 0; j < 8; j++) {
                float v0 = (acc[i][j][half * 2]     + bi) * sc;
                float v1 = (acc[i][j][half * 2 + 1] + bi) * sc;
                uint32_t hp = packbf(v0, v1);
                uint32_t lp = packbf(v0 - __uint_as_float(hp << 16),
                                     v1 - __uint_as_float(hp & 0xFFFF0000u));
                *(uint32_t*)(outh + rowb + j * 8) = hp;
                *(uint32_t*)(outl + rowb + j * 8) = lp;
            }
        }
    }
}

// ---------------------------------------------------------------------------
// Proj GEMM (proven R4 kernel): out fp32 + bias + residual
// ---------------------------------------------------------------------------
#define TILE_B   10240
#define STAGE_B  (4 * TILE_B)
#define GEMM_SMEM (2 * STAGE_B)

__global__ __launch_bounds__(256) void gemm_mma(
        const __nv_bfloat16* __restrict__ Ah, const __nv_bfloat16* __restrict__ Al,
        const __nv_bfloat16* __restrict__ Bh, const __nv_bfloat16* __restrict__ Bl,
        const float* __restrict__ bias, const float* __restrict__ residual,
        float* __restrict__ out, int OC) {
    extern __shared__ char smem[];
    uint32_t smem_u = smem_to_u32(smem);
    int tid = threadIdx.x;
    int warp = tid >> 5, lane = tid & 31;
    int wm = warp & 1, wn = warp >> 1;
    int n0 = blockIdx.x * 128;
    int o0 = blockIdx.y * 128;
    int b  = blockIdx.z;

    const __nv_bfloat16* a0 = Ah + (size_t)o0 * NC;
    const __nv_bfloat16* a1 = Al + (size_t)o0 * NC;
    const __nv_bfloat16* b0 = Bh + ((size_t)b * NHW + n0) * NC;
    const __nv_bfloat16* b1 = Bl + ((size_t)b * NHW + n0) * NC;
    const __nv_bfloat16* srcs[4] = {a0, a1, b0, b1};

    auto load_stage = [&](int chunk, int s) {
        int k0 = chunk * 32;
        uint32_t sbase = smem_u + s * STAGE_B;
        #pragma unroll
        for (int t = 0; t < 8; t++) {
            int tile = t >> 1;
            int c = ((t & 1) << 8) + tid;
            int row = c >> 2, ch = c & 3;
            uint32_t daddr = sbase + tile * TILE_B + row * 80 + ch * 16;
            cp_async16(daddr, srcs[tile] + (size_t)row * NC + k0 + ch * 8);
        }
        CP_COMMIT();
    };

    float acc[4][4][4] = {};
    uint32_t aLane = (uint32_t)((lane & 15) * 80 + (lane >> 4) * 16);
    uint32_t bLane = (uint32_t)(((lane & 7) + ((lane >> 4) << 3)) * 80 + ((lane >> 3) & 1) * 16);

    load_stage(0, 0);
    #pragma unroll 1
    for (int c = 0; c < 16; c++) {
        if (c + 1 < 16) load_stage(c + 1, (c + 1) & 1);
        if (c + 1 < 16) { CP_WAIT(1); } else { CP_WAIT(0); }
        __syncthreads();

        uint32_t sbase = smem_u + (c & 1) * STAGE_B;
        uint32_t offAh = sbase            + (wm * 64) * 80 + aLane;
        uint32_t offAl = sbase + TILE_B   + (wm * 64) * 80 + aLane;
        uint32_t offBh = sbase + 2*TILE_B + (wn * 32) * 80 + bLane;
        uint32_t offBl = sbase + 3*TILE_B + (wn * 32) * 80 + bLane;

        #pragma unroll
        for (int ks = 0; ks < 2; ks++) {
            uint32_t ko = ks * 32;
            uint32_t af[4][4], bh[2][4], bl[2][4];
            #pragma unroll
            for (int i = 0; i < 4; i++) ldsm4(af[i], offAh + i * 16 * 80 + ko);
            #pragma unroll
            for (int g = 0; g < 2; g++) ldsm4(bh[g], offBh + g * 16 * 80 + ko);
            #pragma unroll
            for (int g = 0; g < 2; g++) ldsm4(bl[g], offBl + g * 16 * 80 + ko);
            #pragma unroll
            for (int i = 0; i < 4; i++)
                #pragma unroll
                for (int j = 0; j < 4; j++)
                    mma_bf16(acc[i][j], af[i], &bh[j >> 1][(j & 1) * 2]);
            #pragma unroll
            for (int i = 0; i < 4; i++)
                #pragma unroll
                for (int j = 0; j < 4; j++)
                    mma_bf16(acc[i][j], af[i], &bl[j >> 1][(j & 1) * 2]);
            #pragma unroll
            for (int i = 0; i < 4; i++) ldsm4(af[i], offAl + i * 16 * 80 + ko);
            #pragma unroll
            for (int i = 0; i < 4; i++)
                #pragma unroll
                for (int j = 0; j < 4; j++)
                    mma_bf16(acc[i][j], af[i], &bh[j >> 1][(j & 1) * 2]);
        }
        __syncthreads();
    }

    int r0 = lane >> 2, c0 = (lane & 3) * 2;
    #pragma unroll
    for (int i = 0; i < 4; i++) {
        #pragma unroll
        for (int half = 0; half < 2; half++) {
            int o = o0 + wm * 64 + i * 16 + r0 + half * 8;
            float bi = bias[o];
            size_t rowb = ((size_t)b * OC + o) * NHW + n0 + wn * 32 + c0;
            #pragma unroll
            for (int j = 0; j < 4; j++) {
                float v0 = acc[i][j][half * 2]     + bi;
                float v1 = acc[i][j][half * 2 + 1] + bi;
                size_t off = rowb + j * 8;
                if (residual) {
                    float2 rr = *(const float2*)&residual[off];
                    v0 += rr.x; v1 += rr.y;
                }
                *(float2*)&out[off] = make_float2(v0, v1);
            }
        }
    }
}

// ---------------------------------------------------------------------------
// Flash attention via mma.sync, bf16x3 split (unchanged from R5 — 0.55 mma/cyc)
// ---------------------------------------------------------------------------
#define QSTR 136
#define KSTR 72
#define OSTR 132
#define Q_BYTES   17408
#define KV_TILE_B 9216
#define STAGE0_OFF (2 * Q_BYTES)
#define KV_STAGE_B (4 * KV_TILE_B)
#define ATTN_SMEM (STAGE0_OFF + 2 * KV_STAGE_B)

__global__ __launch_bounds__(256, 2) void attn_mma() {
    extern __shared__ char smem[];
    uint32_t smem_u = smem_to_u32(smem);
    int tid  = threadIdx.x;
    int warp = tid >> 5, lane = tid & 31;
    int wbase = warp * 16;
    int qt = blockIdx.x, h = blockIdx.y, b = blockIdx.z;

    const __nv_bfloat16* gq_h = g_qkvh + ((size_t)b * QC + h * ND) * NHW;
    const __nv_bfloat16* gq_l = g_qkvl + ((size_t)b * QC + h * ND) * NHW;
    const __nv_bfloat16* gk_h = g_qkvh + ((size_t)b * QC + NC + h * ND) * NHW;
    const __nv_bfloat16* gk_l = g_qkvl + ((size_t)b * QC + NC + h * ND) * NHW;
    const __nv_bfloat16* gv_h = g_qkvh + ((size_t)b * QC + 2 * NC + h * ND) * NHW;
    const __nv_bfloat16* gv_l = g_qkvl + ((size_t)b * QC + 2 * NC + h * ND) * NHW;
    const __nv_bfloat16* kvsrc[4] = {gk_h, gk_l, gv_h, gv_l};

    int rowoff = ((lane >> 4) << 3) + (lane & 7);
    int coloff = ((lane >> 3) & 1) * 8;

    auto load_stage = [&](int kt, int s) {
        uint32_t sb = smem_u + STAGE0_OFF + s * KV_STAGE_B;
        #pragma unroll
        for (int k = 0; k < 8; k++) {
            int c = tid + k * 256;
            int tile = c >> 9, row = (c >> 3) & 63, ch = c & 7;
            cp_async16(sb + tile * KV_TILE_B + row * (KSTR * 2) + ch * 16,
                       kvsrc[tile] + (size_t)row * NHW + kt * 64 + ch * 8);
        }
        CP_COMMIT();
    };

    {
        #pragma unroll
        for (int k = 0; k < 8; k++) {
            int c = tid + k * 256;
            int tile = c >> 10, row = (c >> 4) & 63, ch = c & 15;
            const __nv_bfloat16* src = tile ? gq_l : gq_h;
            cp_async16(smem_u + tile * Q_BYTES + row * (QSTR * 2) + ch * 16,
                       src + (size_t)row * NHW + qt * 128 + ch * 8);
        }
    }
    load_stage(0, 0);

    float m0 = -1e30f, m1 = -1e30f, l0 = 0.f, l1 = 0.f;
    float oacc[8][4] = {};

    uint32_t qAddrH = smem_u + (uint32_t)(rowoff * (QSTR * 2) + (wbase + coloff) * 2);
    uint32_t qAddrL = qAddrH + Q_BYTES;

    #pragma unroll 1
    for (int kt = 0; kt < 16; kt++) {
        CP_WAIT(0);
        __syncthreads();
        if (kt < 15) load_stage(kt + 1, (kt + 1) & 1);

        uint32_t sb = smem_u + STAGE0_OFF + (kt & 1) * KV_STAGE_B;
        float sacc[8][4] = {};
        #pragma unroll
        for (int kc = 0; kc < 4; kc++) {
            uint32_t qh[4], ql[4];
            ldsm4t(qh, qAddrH + kc * 16 * (QSTR * 2));
            ldsm4t(ql, qAddrL + kc * 16 * (QSTR * 2));
            uint32_t kBase = sb + (uint32_t)((kc * 16 + rowoff) * (KSTR * 2) + coloff * 2);
            #pragma unroll
            for (int ko2 = 0; ko2 < 4; ko2++) {
                uint32_t kh[4], kl[4];
                ldsm4t(kh, kBase + ko2 * 32);
                ldsm4t(kl, kBase + KV_TILE_B + ko2 * 32);
                mma4(sacc[2*ko2],   qh[0],qh[1],qh[2],qh[3], kh[0], kh[2]);
                mma4(sacc[2*ko2+1], qh[0],qh[1],qh[2],qh[3], kh[1], kh[3]);
                mma4(sacc[2*ko2],   qh[0],qh[1],qh[2],qh[3], kl[0], kl[2]);
                mma4(sacc[2*ko2+1], qh[0],qh[1],qh[2],qh[3], kl[1], kl[3]);
                mma4(sacc[2*ko2],   ql[0],ql[1],ql[2],ql[3], kh[0], kh[2]);
                mma4(sacc[2*ko2+1], ql[0],ql[1],ql[2],ql[3], kh[1], kh[3]);
            }
        }

        float tm0 = -1e30f, tm1 = -1e30f;
        #pragma unroll
        for (int j = 0; j < 8; j++) {
            tm0 = fmaxf(tm0, fmaxf(sacc[j][0], sacc[j][1]));
            tm1 = fmaxf(tm1, fmaxf(sacc[j][2], sacc[j][3]));
        }
        tm0 = fmaxf(tm0, __shfl_xor_sync(0xFFFFFFFFu, tm0, 1));
        tm0 = fmaxf(tm0, __shfl_xor_sync(0xFFFFFFFFu, tm0, 2));
        tm1 = fmaxf(tm1, __shfl_xor_sync(0xFFFFFFFFu, tm1, 1));
        tm1 = fmaxf(tm1, __shfl_xor_sync(0xFFFFFFFFu, tm1, 2));
        float nm0 = fmaxf(m0, tm0), nm1 = fmaxf(m1, tm1);
        float al0 = __expf(m0 - nm0), al1 = __expf(m1 - nm1);
        m0 = nm0; m1 = nm1;
        float sum0 = 0.f, sum1 = 0.f;
        #pragma unroll
        for (int j = 0; j < 8; j++) {
            sacc[j][0] = __expf(sacc[j][0] - m0); sum0 += sacc[j][0];
            sacc[j][1] = __expf(sacc[j][1] - m0); sum0 += sacc[j][1];
            sacc[j][2] = __expf(sacc[j][2] - m1); sum1 += sacc[j][2];
            sacc[j][3] = __expf(sacc[j][3] - m1); sum1 += sacc[j][3];
        }
        sum0 += __shfl_xor_sync(0xFFFFFFFFu, sum0, 1);
        sum0 += __shfl_xor_sync(0xFFFFFFFFu, sum0, 2);
        sum1 += __shfl_xor_sync(0xFFFFFFFFu, sum1, 1);
        sum1 += __shfl_xor_sync(0xFFFFFFFFu, sum1, 2);
        l0 = l0 * al0 + sum0;
        l1 = l1 * al1 + sum1;
        #pragma unroll
        for (int d = 0; d < 8; d++) {
            oacc[d][0] *= al0; oacc[d][1] *= al0;
            oacc[d][2] *= al1; oacc[d][3] *= al1;
        }

        uint32_t vB = sb + 2 * KV_TILE_B;
        #pragma unroll
        for (int kc2 = 0; kc2 < 4; kc2++) {
            int j0 = 2 * kc2, j1 = j0 + 1;
            uint32_t pa0 = packbf(sacc[j0][0], sacc[j0][1]);
            uint32_t pa1 = packbf(sacc[j0][2], sacc[j0][3]);
            uint32_t pa2 = packbf(sacc[j1][0], sacc[j1][1]);
            uint32_t pa3 = packbf(sacc[j1][2], sacc[j1][3]);
            uint32_t pl0 = packbf(sacc[j0][0] - __uint_as_float(pa0 << 16),
                                  sacc[j0][1] - __uint_as_float(pa0 & 0xFFFF0000u));
            uint32_t pl1 = packbf(sacc[j0][2] - __uint_as_float(pa1 << 16),
                                  sacc[j0][3] - __uint_as_float(pa1 & 0xFFFF0000u));
            uint32_t pl2 = packbf(sacc[j1][0] - __uint_as_float(pa2 << 16),
                                  sacc[j1][1] - __uint_as_float(pa2 & 0xFFFF0000u));
            uint32_t pl3 = packbf(sacc[j1][2] - __uint_as_float(pa3 << 16),
                                  sacc[j1][3] - __uint_as_float(pa3 & 0xFFFF0000u));
            uint32_t vCol = (uint32_t)((kc2 * 16 + coloff) * 2);
            #pragma unroll
            for (int do2 = 0; do2 < 4; do2++) {
                uint32_t vh[4], vl[4];
                uint32_t vRow = (uint32_t)((do2 * 16 + rowoff) * (KSTR * 2));
                ldsm4(vh, vB + vRow + vCol);
                ldsm4(vl, vB + KV_TILE_B + vRow + vCol);
                mma4(oacc[2*do2],   pa0,pa1,pa2,pa3, vh[0], vh[1]);
                mma4(oacc[2*do2+1], pa0,pa1,pa2,pa3, vh[2], vh[3]);
                mma4(oacc[2*do2],   pl0,pl1,pl2,pl3, vh[0], vh[1]);
                mma4(oacc[2*do2+1], pl0,pl1,pl2,pl3, vh[2], vh[3]);
                mma4(oacc[2*do2],   pa0,pa1,pa2,pa3, vl[0], vl[1]);
                mma4(oacc[2*do2+1], pa0,pa1,pa2,pa3, vl[2], vl[3]);
            }
        }
    }

    float* Os = (float*)(smem + STAGE0_OFF);
    float linv0 = 1.f / l0, linv1 = 1.f / l1;
    int r0q = wbase + (lane >> 2);
    int ddc = (lane & 3) * 2;
    #pragma unroll
    for (int d = 0; d < 8; d++) {
        Os[(d * 8 + ddc)     * OSTR + r0q]     = oacc[d][0] * linv0;
        Os[(d * 8 + ddc + 1) * OSTR + r0q]     = oacc[d][1] * linv0;
        Os[(d * 8 + ddc)     * OSTR + r0q + 8] = oacc[d][2] * linv1;
        Os[(d * 8 + ddc + 1) * OSTR + r0q + 8] = oacc[d][3] * linv1;
    }
    __syncthreads();

    {
        int q = tid >> 1;
        int ddb = (tid & 1) * 32;
        uint32_t hb[16], lb[16];
        #pragma unroll
        for (int d = 0; d < 32; d += 2) {
            float f0 = Os[(ddb + d)     * OSTR + q];
            float f1 = Os[(ddb + d + 1) * OSTR + q];
            uint32_t hp = packbf(f0, f1);
            hb[d >> 1] = hp;
            lb[d >> 1] = packbf(f0 - __uint_as_float(hp << 16),
                                f1 - __uint_as_float(hp & 0xFFFF0000u));
        }
        size_t base = ((size_t)b * NHW + qt * 128 + q) * NC + h * 64 + ddb;
        #pragma unroll
        for (int u = 0; u < 4; u++) {
            *(uint4*)(g_aoh + base + u * 8) = *(uint4*)&hb[u * 4];
            *(uint4*)(g_aol + base + u * 8) = *(uint4*)&lb[u * 4];
        }
    }
}

// ---------------------------------------------------------------------------
extern "C" void kernel_launch(void* const* d_in, const int* in_sizes, int n_in,
                              void* d_out, int out_size) {
    const float* x      = (const float*)d_in[0];
    const float* gn_w   = (const float*)d_in[1];
    const float* gn_b   = (const float*)d_in[2];
    const float* qkv_w  = (const float*)d_in[3];
    const float* qkv_b  = (const float*)d_in[4];
    const float* proj_w = (const float*)d_in[5];
    const float* proj_b = (const float*)d_in[6];
    float* out = (float*)d_out;

    cudaFuncSetAttribute(qkv_gemm2, cudaFuncAttributeMaxDynamicSharedMemorySize, QKV_SMEM);
    cudaFuncSetAttribute(gemm_mma, cudaFuncAttributeMaxDynamicSharedMemorySize, GEMM_SMEM);
    cudaFuncSetAttribute(attn_mma, cudaFuncAttributeMaxDynamicSharedMemorySize, ATTN_SMEM);

    __nv_bfloat16 *qwh, *qwl, *pwh, *pwl, *xh, *xl, *aoh, *aol, *qkvh, *qkvl;
    cudaGetSymbolAddress((void**)&qwh, g_qwh);
    cudaGetSymbolAddress((void**)&qwl, g_qwl);
    cudaGetSymbolAddress((void**)&pwh, g_pwh);
    cudaGetSymbolAddress((void**)&pwl, g_pwl);
    cudaGetSymbolAddress((void**)&xh,  g_xh);
    cudaGetSymbolAddress((void**)&xl,  g_xl);
    cudaGetSymbolAddress((void**)&aoh, g_aoh);
    cudaGetSymbolAddress((void**)&aol, g_aol);
    cudaGetSymbolAddress((void**)&qkvh, g_qkvh);
    cudaGetSymbolAddress((void**)&qkvl, g_qkvl);
    float *xnp;
    cudaGetSymbolAddress((void**)&xnp, g_xn);

    // 1. GroupNorm
    gn_kernel<<<NB * 8, 512>>>(x, gn_w, gn_b);
    // 2. Weight conversion (bf16 hi/lo)
    convert_w<<<(QC * NC + 255) / 256, 256>>>(qkv_w, qwh, qwl, QC * NC);
    convert_w<<<(NC * NC + 255) / 256, 256>>>(proj_w, pwh, pwl, NC * NC);
    // 3. Transpose+convert xn -> [b][n][c] bf16 hi/lo
    convert_t<<<dim3(NHW / 32, NC / 32, NB), dim3(32, 8)>>>(xnp, xh, xl);
    // 4. QKV GEMM: 3-stage pipeline, writes bf16 hi/lo directly (Q scaled)
    qkv_gemm2<<<dim3(NHW / 256, QC / 128, NB), 256, QKV_SMEM>>>(
        qwh, qwl, xh, xl, qkv_b, qkvh, qkvl);
    // 5. Flash attention (mma.sync), writes g_aoh/g_aol in [b][n][c]
    attn_mma<<<dim3(NHW / 128, NHEADS, NB), 256, ATTN_SMEM>>>();
    // 6. Proj GEMM + bias + residual
    gemm_mma<<<dim3(NHW / 128, NC / 128, NB), 256, GEMM_SMEM>>>(
        pwh, pwl, aoh, aol, proj_b, x, out, NC);
}

// round 7
// speedup vs baseline: 3.0169x; 1.1016x over previous
#include <cuda_runtime.h>
#include <cuda_bf16.h>
#include <cstdint>
#include <math.h>

// Problem constants
#define NB     16
#define NC     512
#define NHW    1024
#define NHEADS 8
#define ND     64
#define QC     1536     // 3*NC
#define GN_EPS 1e-5f

// ===========================================================================
// Warp-level MMA helpers (sm_80+ paths — legal on base sm_100)
// ===========================================================================
__device__ __forceinline__ uint32_t smem_to_u32(const void* p) {
    uint32_t a;
    asm("{ .reg .u64 t; cvta.to.shared.u64 t, %1; cvt.u32.u64 %0, t; }" : "=r"(a) : "l"(p));
    return a;
}
__device__ __forceinline__ void ldsm4(uint32_t* r, uint32_t addr) {
    asm volatile("ldmatrix.sync.aligned.m8n8.x4.shared.b16 {%0,%1,%2,%3}, [%4];"
                 : "=r"(r[0]), "=r"(r[1]), "=r"(r[2]), "=r"(r[3]) : "r"(addr));
}
__device__ __forceinline__ void ldsm4t(uint32_t* r, uint32_t addr) {
    asm volatile("ldmatrix.sync.aligned.m8n8.x4.trans.shared.b16 {%0,%1,%2,%3}, [%4];"
                 : "=r"(r[0]), "=r"(r[1]), "=r"(r[2]), "=r"(r[3]) : "r"(addr));
}
__device__ __forceinline__ void mma_bf16(float* d, const uint32_t* a, const uint32_t* b) {
    asm volatile("mma.sync.aligned.m16n8k16.row.col.f32.bf16.bf16.f32 "
                 "{%0,%1,%2,%3}, {%4,%5,%6,%7}, {%8,%9}, {%0,%1,%2,%3};"
                 : "+f"(d[0]), "+f"(d[1]), "+f"(d[2]), "+f"(d[3])
                 : "r"(a[0]), "r"(a[1]), "r"(a[2]), "r"(a[3]), "r"(b[0]), "r"(b[1]));
}
__device__ __forceinline__ void mma4(float* d, uint32_t a0, uint32_t a1, uint32_t a2,
                                     uint32_t a3, uint32_t b0, uint32_t b1) {
    asm volatile("mma.sync.aligned.m16n8k16.row.col.f32.bf16.bf16.f32 "
                 "{%0,%1,%2,%3}, {%4,%5,%6,%7}, {%8,%9}, {%0,%1,%2,%3};"
                 : "+f"(d[0]), "+f"(d[1]), "+f"(d[2]), "+f"(d[3])
                 : "r"(a0), "r"(a1), "r"(a2), "r"(a3), "r"(b0), "r"(b1));
}
__device__ __forceinline__ void cp_async16(uint32_t daddr, const void* g) {
    asm volatile("cp.async.cg.shared.global [%0], [%1], 16;" :: "r"(daddr), "l"(g));
}
#define CP_COMMIT() asm volatile("cp.async.commit_group;" ::: "memory")
#define CP_WAIT(N)  asm volatile("cp.async.wait_group %0;" :: "n"(N) : "memory")

// pack two fp32 -> bf16x2 (lo first)
__device__ __forceinline__ uint32_t packbf(float lo, float hi) {
    uint32_t r;
    asm("cvt.rn.bf16x2.f32 %0, %1, %2;" : "=r"(r) : "f"(hi), "f"(lo));
    return r;
}

// ===========================================================================
// Scratch (device globals — no allocation allowed)
// ===========================================================================
__device__ float g_xn [NB * NC * NHW];               // groupnorm out [b][c][n]
__device__ __nv_bfloat16 g_xh [NB * NHW * NC];       // xn transposed hi [b][n][c]
__device__ __nv_bfloat16 g_xl [NB * NHW * NC];       // xn transposed lo
__device__ __nv_bfloat16 g_aoh[NB * NHW * NC];       // attn out hi [b][n][c]
__device__ __nv_bfloat16 g_aol[NB * NHW * NC];       // attn out lo
__device__ __nv_bfloat16 g_qkvh[NB * QC * NHW];      // qkv hi [b][o][n] (Q pre-scaled)
__device__ __nv_bfloat16 g_qkvl[NB * QC * NHW];      // qkv lo
__device__ __nv_bfloat16 g_qwh[QC * NC];             // qkv_w hi  [o][c]
__device__ __nv_bfloat16 g_qwl[QC * NC];
__device__ __nv_bfloat16 g_pwh[NC * NC];             // proj_w hi
__device__ __nv_bfloat16 g_pwl[NC * NC];

// ---------------------------------------------------------------------------
// Kernel 1: GroupNorm
// ---------------------------------------------------------------------------
__global__ __launch_bounds__(512) void gn_kernel(const float* __restrict__ x,
                                                 const float* __restrict__ gw,
                                                 const float* __restrict__ gb) {
    int bg = blockIdx.x;
    int b = bg >> 3, g = bg & 7;
    const float4* xp = (const float4*)(x + (size_t)(b * NC + g * 64) * NHW);
    float4* op = (float4*)(g_xn + (size_t)(b * NC + g * 64) * NHW);
    const int NE4 = 64 * NHW / 4;
    int tid = threadIdx.x;

    float s = 0.f, s2 = 0.f;
    for (int i = tid; i < NE4; i += 512) {
        float4 v = xp[i];
        s  += v.x + v.y + v.z + v.w;
        s2 += v.x * v.x + v.y * v.y + v.z * v.z + v.w * v.w;
    }
    __shared__ float rs[16], rs2[16];
    #pragma unroll
    for (int o = 16; o > 0; o >>= 1) {
        s  += __shfl_down_sync(0xFFFFFFFFu, s, o);
        s2 += __shfl_down_sync(0xFFFFFFFFu, s2, o);
    }
    int w = tid >> 5, l = tid & 31;
    if (l == 0) { rs[w] = s; rs2[w] = s2; }
    __syncthreads();
    __shared__ float sh_mean, sh_rstd;
    if (tid == 0) {
        float S = 0.f, S2 = 0.f;
        #pragma unroll
        for (int i = 0; i < 16; i++) { S += rs[i]; S2 += rs2[i]; }
        float mean = S * (1.f / 65536.f);
        float var  = S2 * (1.f / 65536.f) - mean * mean;
        sh_mean = mean;
        sh_rstd = rsqrtf(var + GN_EPS);
    }
    __syncthreads();
    float mean = sh_mean, rstd = sh_rstd;
    for (int i = tid; i < NE4; i += 512) {
        int c = g * 64 + (i >> 8);
        float sc = gw[c] * rstd;
        float bi = gb[c] - mean * sc;
        float4 v = xp[i];
        v.x = v.x * sc + bi; v.y = v.y * sc + bi;
        v.z = v.z * sc + bi; v.w = v.w * sc + bi;
        op[i] = v;
    }
}

// ---------------------------------------------------------------------------
// Convert weights fp32 -> bf16 hi/lo (same layout)
// ---------------------------------------------------------------------------
__global__ void convert_w(const float* __restrict__ src, __nv_bfloat16* __restrict__ dh,
                          __nv_bfloat16* __restrict__ dl, int n) {
    int i = blockIdx.x * 256 + threadIdx.x;
    if (i < n) {
        float v = src[i];
        __nv_bfloat16 h = __float2bfloat16(v);
        dh[i] = h;
        dl[i] = __float2bfloat16(v - __bfloat162float(h));
    }
}

// ---------------------------------------------------------------------------
// Transpose+convert: src fp32 [b][c][n] -> dh/dl bf16 [b][n][c]
// ---------------------------------------------------------------------------
__global__ __launch_bounds__(256) void convert_t(const float* __restrict__ src,
                                                 __nv_bfloat16* __restrict__ dh,
                                                 __nv_bfloat16* __restrict__ dl) {
    __shared__ float t[32][33];
    int tx = threadIdx.x, ty = threadIdx.y;
    int n0 = blockIdx.x * 32, c0 = blockIdx.y * 32, b = blockIdx.z;
    const float* s = src + ((size_t)b * NC + c0) * NHW + n0;
    #pragma unroll
    for (int i = 0; i < 4; i++)
        t[ty + 8 * i][tx] = s[(size_t)(ty + 8 * i) * NHW + tx];
    __syncthreads();
    size_t ob = ((size_t)b * NHW + n0) * NC + c0;
    #pragma unroll
    for (int i = 0; i < 4; i++) {
        float v = t[tx][ty + 8 * i];
        __nv_bfloat16 h = __float2bfloat16(v);
        size_t o = ob + (size_t)(ty + 8 * i) * NC + tx;
        dh[o] = h;
        dl[o] = __float2bfloat16(v - __bfloat162float(h));
    }
}

// ---------------------------------------------------------------------------
// GEMM v3 core: CTA 128(o) x 128(n), 4 warps (2x2), warp tile 64x64.
// 192 mma per warp per barrier (attention-density). 2-stage cp.async, 80KB,
// 2 CTAs/SM. bf16x3 split. Shared mainloop; two epilogues.
// ---------------------------------------------------------------------------
#define G3_TILE_B  10240              // 128 rows x 80B
#define G3_STAGE_B (4 * G3_TILE_B)    // 40960
#define G3_SMEM    (2 * G3_STAGE_B)   // 81920

// mainloop macro: leaves acc[4][8][4] computed; expects a0,a1,b0,b1 row ptrs
#define G3_MAINLOOP()                                                          \
    const __nv_bfloat16* srcs[4] = {a0, a1, b0, b1};                           \
    auto load_stage = [&](int chunk, int s) {                                  \
        int k0 = chunk * 32;                                                   \
        uint32_t sbase = smem_u + s * G3_STAGE_B;                              \
        _Pragma("unroll")                                                      \
        for (int t = 0; t < 16; t++) {                                         \
            int idx = t * 128 + tid;                                           \
            int tile = idx >> 9;                                               \
            int r = (idx >> 2) & 127;                                          \
            int ch = idx & 3;                                                  \
            cp_async16(sbase + tile * G3_TILE_B + r * 80 + ch * 16,            \
                       srcs[tile] + (size_t)r * NC + k0 + ch * 8);             \
        }                                                                      \
        CP_COMMIT();                                                           \
    };                                                                         \
    float acc[4][8][4] = {};                                                   \
    uint32_t aLane = (uint32_t)((lane & 15) * 80 + (lane >> 4) * 16);          \
    uint32_t bLane = (uint32_t)(((lane & 7) + ((lane >> 4) << 3)) * 80 +       \
                                ((lane >> 3) & 1) * 16);                       \
    load_stage(0, 0);                                                          \
    _Pragma("unroll 1")                                                        \
    for (int c = 0; c < 16; c++) {                                             \
        if (c + 1 < 16) { load_stage(c + 1, (c + 1) & 1); CP_WAIT(1); }        \
        else { CP_WAIT(0); }                                                   \
        __syncthreads();                                                       \
        uint32_t sb = smem_u + (c & 1) * G3_STAGE_B;                           \
        uint32_t offAh = sb                 + (wm * 64) * 80 + aLane;          \
        uint32_t offAl = sb + G3_TILE_B     + (wm * 64) * 80 + aLane;          \
        uint32_t offBh = sb + 2 * G3_TILE_B + (wn * 64) * 80 + bLane;          \
        uint32_t offBl = offBh + G3_TILE_B;                                    \
        _Pragma("unroll")                                                      \
        for (int ks = 0; ks < 2; ks++) {                                       \
            uint32_t ko = ks * 32;                                             \
            uint32_t af[4][4], bh[4][4], bl[4][4];                             \
            _Pragma("unroll")                                                  \
            for (int i = 0; i < 4; i++) ldsm4(af[i], offAh + i * 16 * 80 + ko);\
            _Pragma("unroll")                                                  \
            for (int g = 0; g < 4; g++) ldsm4(bh[g], offBh + g * 16 * 80 + ko);\
            _Pragma("unroll")                                                  \
            for (int g = 0; g < 4; g++) ldsm4(bl[g], offBl + g * 16 * 80 + ko);\
            _Pragma("unroll")                                                  \
            for (int i = 0; i < 4; i++)                                        \
                _Pragma("unroll")                                              \
                for (int j = 0; j < 8; j++)                                    \
                    mma_bf16(acc[i][j], af[i], &bh[j >> 1][(j & 1) * 2]);      \
            _Pragma("unroll")                                                  \
            for (int i = 0; i < 4; i++)                                        \
                _Pragma("unroll")                                              \
                for (int j = 0; j < 8; j++)                                    \
                    mma_bf16(acc[i][j], af[i], &bl[j >> 1][(j & 1) * 2]);      \
            _Pragma("unroll")                                                  \
            for (int i = 0; i < 4; i++) ldsm4(af[i], offAl + i * 16 * 80 + ko);\
            _Pragma("unroll")                                                  \
            for (int i = 0; i < 4; i++)                                        \
                _Pragma("unroll")                                              \
                for (int j = 0; j < 8; j++)                                    \
                    mma_bf16(acc[i][j], af[i], &bh[j >> 1][(j & 1) * 2]);      \
        }                                                                      \
        __syncthreads();                                                       \
    }

// QKV: writes bf16 hi/lo in [b][o][n], Q rows (o<NC) scaled by 0.125
__global__ __launch_bounds__(128, 2) void qkv_gemm3(
        const __nv_bfloat16* __restrict__ Ah, const __nv_bfloat16* __restrict__ Al,
        const __nv_bfloat16* __restrict__ Bh, const __nv_bfloat16* __restrict__ Bl,
        const float* __restrict__ bias,
        __nv_bfloat16* __restrict__ outh, __nv_bfloat16* __restrict__ outl) {
    extern __shared__ char smem[];
    uint32_t smem_u = smem_to_u32(smem);
    int tid = threadIdx.x;
    int warp = tid >> 5, lane = tid & 31;
    int wm = warp & 1, wn = warp >> 1;     // 2(o) x 2(n)
    int n0 = blockIdx.x * 128;
    int o0 = blockIdx.y * 128;
    int b  = blockIdx.z;

    const __nv_bfloat16* a0 = Ah + (size_t)o0 * NC;
    const __nv_bfloat16* a1 = Al + (size_t)o0 * NC;
    const __nv_bfloat16* b0 = Bh + ((size_t)b * NHW + n0) * NC;
    const __nv_bfloat16* b1 = Bl + ((size_t)b * NHW + n0) * NC;

    G3_MAINLOOP();

    int r0 = lane >> 2, c0 = (lane & 3) * 2;
    #pragma unroll
    for (int i = 0; i < 4; i++) {
        #pragma unroll
        for (int half = 0; half < 2; half++) {
            int o = o0 + wm * 64 + i * 16 + r0 + half * 8;
            float bi = bias[o];
            float sc = (o < NC) ? 0.125f : 1.0f;
            size_t rowb = ((size_t)b * QC + o) * NHW + n0 + wn * 64 + c0;
            #pragma unroll
            for (int j = 0; j < 8; j++) {
                float v0 = (acc[i][j][half * 2]     + bi) * sc;
                float v1 = (acc[i][j][half * 2 + 1] + bi) * sc;
                uint32_t hp = packbf(v0, v1);
                uint32_t lp = packbf(v0 - __uint_as_float(hp << 16),
                                     v1 - __uint_as_float(hp & 0xFFFF0000u));
                *(uint32_t*)(outh + rowb + j * 8) = hp;
                *(uint32_t*)(outl + rowb + j * 8) = lp;
            }
        }
    }
}

// Proj: fp32 out + bias + residual
__global__ __launch_bounds__(128, 2) void proj_gemm3(
        const __nv_bfloat16* __restrict__ Ah, const __nv_bfloat16* __restrict__ Al,
        const __nv_bfloat16* __restrict__ Bh, const __nv_bfloat16* __restrict__ Bl,
        const float* __restrict__ bias, const float* __restrict__ residual,
        float* __restrict__ out) {
    extern __shared__ char smem[];
    uint32_t smem_u = smem_to_u32(smem);
    int tid = threadIdx.x;
    int warp = tid >> 5, lane = tid & 31;
    int wm = warp & 1, wn = warp >> 1;
    int n0 = blockIdx.x * 128;
    int o0 = blockIdx.y * 128;
    int b  = blockIdx.z;

    const __nv_bfloat16* a0 = Ah + (size_t)o0 * NC;
    const __nv_bfloat16* a1 = Al + (size_t)o0 * NC;
    const __nv_bfloat16* b0 = Bh + ((size_t)b * NHW + n0) * NC;
    const __nv_bfloat16* b1 = Bl + ((size_t)b * NHW + n0) * NC;

    G3_MAINLOOP();

    int r0 = lane >> 2, c0 = (lane & 3) * 2;
    #pragma unroll
    for (int i = 0; i < 4; i++) {
        #pragma unroll
        for (int half = 0; half < 2; half++) {
            int o = o0 + wm * 64 + i * 16 + r0 + half * 8;
            float bi = bias[o];
            size_t rowb = ((size_t)b * NC + o) * NHW + n0 + wn * 64 + c0;
            #pragma unroll
            for (int j = 0; j < 8; j++) {
                float v0 = acc[i][j][half * 2]     + bi;
                float v1 = acc[i][j][half * 2 + 1] + bi;
                size_t off = rowb + j * 8;
                float2 rr = *(const float2*)&residual[off];
                *(float2*)&out[off] = make_float2(v0 + rr.x, v1 + rr.y);
            }
        }
    }
}

// ---------------------------------------------------------------------------
// Flash attention via mma.sync, bf16x3 split (unchanged — 0.49 mma/cyc/SM)
// ---------------------------------------------------------------------------
#define QSTR 136
#define KSTR 72
#define OSTR 132
#define Q_BYTES   17408
#define KV_TILE_B 9216
#define STAGE0_OFF (2 * Q_BYTES)
#define KV_STAGE_B (4 * KV_TILE_B)
#define ATTN_SMEM (STAGE0_OFF + 2 * KV_STAGE_B)

__global__ __launch_bounds__(256, 2) void attn_mma() {
    extern __shared__ char smem[];
    uint32_t smem_u = smem_to_u32(smem);
    int tid  = threadIdx.x;
    int warp = tid >> 5, lane = tid & 31;
    int wbase = warp * 16;
    int qt = blockIdx.x, h = blockIdx.y, b = blockIdx.z;

    const __nv_bfloat16* gq_h = g_qkvh + ((size_t)b * QC + h * ND) * NHW;
    const __nv_bfloat16* gq_l = g_qkvl + ((size_t)b * QC + h * ND) * NHW;
    const __nv_bfloat16* gk_h = g_qkvh + ((size_t)b * QC + NC + h * ND) * NHW;
    const __nv_bfloat16* gk_l = g_qkvl + ((size_t)b * QC + NC + h * ND) * NHW;
    const __nv_bfloat16* gv_h = g_qkvh + ((size_t)b * QC + 2 * NC + h * ND) * NHW;
    const __nv_bfloat16* gv_l = g_qkvl + ((size_t)b * QC + 2 * NC + h * ND) * NHW;
    const __nv_bfloat16* kvsrc[4] = {gk_h, gk_l, gv_h, gv_l};

    int rowoff = ((lane >> 4) << 3) + (lane & 7);
    int coloff = ((lane >> 3) & 1) * 8;

    auto load_stage = [&](int kt, int s) {
        uint32_t sb = smem_u + STAGE0_OFF + s * KV_STAGE_B;
        #pragma unroll
        for (int k = 0; k < 8; k++) {
            int c = tid + k * 256;
            int tile = c >> 9, row = (c >> 3) & 63, ch = c & 7;
            cp_async16(sb + tile * KV_TILE_B + row * (KSTR * 2) + ch * 16,
                       kvsrc[tile] + (size_t)row * NHW + kt * 64 + ch * 8);
        }
        CP_COMMIT();
    };

    {
        #pragma unroll
        for (int k = 0; k < 8; k++) {
            int c = tid + k * 256;
            int tile = c >> 10, row = (c >> 4) & 63, ch = c & 15;
            const __nv_bfloat16* src = tile ? gq_l : gq_h;
            cp_async16(smem_u + tile * Q_BYTES + row * (QSTR * 2) + ch * 16,
                       src + (size_t)row * NHW + qt * 128 + ch * 8);
        }
    }
    load_stage(0, 0);

    float m0 = -1e30f, m1 = -1e30f, l0 = 0.f, l1 = 0.f;
    float oacc[8][4] = {};

    uint32_t qAddrH = smem_u + (uint32_t)(rowoff * (QSTR * 2) + (wbase + coloff) * 2);
    uint32_t qAddrL = qAddrH + Q_BYTES;

    #pragma unroll 1
    for (int kt = 0; kt < 16; kt++) {
        CP_WAIT(0);
        __syncthreads();
        if (kt < 15) load_stage(kt + 1, (kt + 1) & 1);

        uint32_t sb = smem_u + STAGE0_OFF + (kt & 1) * KV_STAGE_B;
        float sacc[8][4] = {};
        #pragma unroll
        for (int kc = 0; kc < 4; kc++) {
            uint32_t qh[4], ql[4];
            ldsm4t(qh, qAddrH + kc * 16 * (QSTR * 2));
            ldsm4t(ql, qAddrL + kc * 16 * (QSTR * 2));
            uint32_t kBase = sb + (uint32_t)((kc * 16 + rowoff) * (KSTR * 2) + coloff * 2);
            #pragma unroll
            for (int ko2 = 0; ko2 < 4; ko2++) {
                uint32_t kh[4], kl[4];
                ldsm4t(kh, kBase + ko2 * 32);
                ldsm4t(kl, kBase + KV_TILE_B + ko2 * 32);
                mma4(sacc[2*ko2],   qh[0],qh[1],qh[2],qh[3], kh[0], kh[2]);
                mma4(sacc[2*ko2+1], qh[0],qh[1],qh[2],qh[3], kh[1], kh[3]);
                mma4(sacc[2*ko2],   qh[0],qh[1],qh[2],qh[3], kl[0], kl[2]);
                mma4(sacc[2*ko2+1], qh[0],qh[1],qh[2],qh[3], kl[1], kl[3]);
                mma4(sacc[2*ko2],   ql[0],ql[1],ql[2],ql[3], kh[0], kh[2]);
                mma4(sacc[2*ko2+1], ql[0],ql[1],ql[2],ql[3], kh[1], kh[3]);
            }
        }

        float tm0 = -1e30f, tm1 = -1e30f;
        #pragma unroll
        for (int j = 0; j < 8; j++) {
            tm0 = fmaxf(tm0, fmaxf(sacc[j][0], sacc[j][1]));
            tm1 = fmaxf(tm1, fmaxf(sacc[j][2], sacc[j][3]));
        }
        tm0 = fmaxf(tm0, __shfl_xor_sync(0xFFFFFFFFu, tm0, 1));
        tm0 = fmaxf(tm0, __shfl_xor_sync(0xFFFFFFFFu, tm0, 2));
        tm1 = fmaxf(tm1, __shfl_xor_sync(0xFFFFFFFFu, tm1, 1));
        tm1 = fmaxf(tm1, __shfl_xor_sync(0xFFFFFFFFu, tm1, 2));
        float nm0 = fmaxf(m0, tm0), nm1 = fmaxf(m1, tm1);
        float al0 = __expf(m0 - nm0), al1 = __expf(m1 - nm1);
        m0 = nm0; m1 = nm1;
        float sum0 = 0.f, sum1 = 0.f;
        #pragma unroll
        for (int j = 0; j < 8; j++) {
            sacc[j][0] = __expf(sacc[j][0] - m0); sum0 += sacc[j][0];
            sacc[j][1] = __expf(sacc[j][1] - m0); sum0 += sacc[j][1];
            sacc[j][2] = __expf(sacc[j][2] - m1); sum1 += sacc[j][2];
            sacc[j][3] = __expf(sacc[j][3] - m1); sum1 += sacc[j][3];
        }
        sum0 += __shfl_xor_sync(0xFFFFFFFFu, sum0, 1);
        sum0 += __shfl_xor_sync(0xFFFFFFFFu, sum0, 2);
        sum1 += __shfl_xor_sync(0xFFFFFFFFu, sum1, 1);
        sum1 += __shfl_xor_sync(0xFFFFFFFFu, sum1, 2);
        l0 = l0 * al0 + sum0;
        l1 = l1 * al1 + sum1;
        #pragma unroll
        for (int d = 0; d < 8; d++) {
            oacc[d][0] *= al0; oacc[d][1] *= al0;
            oacc[d][2] *= al1; oacc[d][3] *= al1;
        }

        uint32_t vB = sb + 2 * KV_TILE_B;
        #pragma unroll
        for (int kc2 = 0; kc2 < 4; kc2++) {
            int j0 = 2 * kc2, j1 = j0 + 1;
            uint32_t pa0 = packbf(sacc[j0][0], sacc[j0][1]);
            uint32_t pa1 = packbf(sacc[j0][2], sacc[j0][3]);
            uint32_t pa2 = packbf(sacc[j1][0], sacc[j1][1]);
            uint32_t pa3 = packbf(sacc[j1][2], sacc[j1][3]);
            uint32_t pl0 = packbf(sacc[j0][0] - __uint_as_float(pa0 << 16),
                                  sacc[j0][1] - __uint_as_float(pa0 & 0xFFFF0000u));
            uint32_t pl1 = packbf(sacc[j0][2] - __uint_as_float(pa1 << 16),
                                  sacc[j0][3] - __uint_as_float(pa1 & 0xFFFF0000u));
            uint32_t pl2 = packbf(sacc[j1][0] - __uint_as_float(pa2 << 16),
                                  sacc[j1][1] - __uint_as_float(pa2 & 0xFFFF0000u));
            uint32_t pl3 = packbf(sacc[j1][2] - __uint_as_float(pa3 << 16),
                                  sacc[j1][3] - __uint_as_float(pa3 & 0xFFFF0000u));
            uint32_t vCol = (uint32_t)((kc2 * 16 + coloff) * 2);
            #pragma unroll
            for (int do2 = 0; do2 < 4; do2++) {
                uint32_t vh[4], vl[4];
                uint32_t vRow = (uint32_t)((do2 * 16 + rowoff) * (KSTR * 2));
                ldsm4(vh, vB + vRow + vCol);
                ldsm4(vl, vB + KV_TILE_B + vRow + vCol);
                mma4(oacc[2*do2],   pa0,pa1,pa2,pa3, vh[0], vh[1]);
                mma4(oacc[2*do2+1], pa0,pa1,pa2,pa3, vh[2], vh[3]);
                mma4(oacc[2*do2],   pl0,pl1,pl2,pl3, vh[0], vh[1]);
                mma4(oacc[2*do2+1], pl0,pl1,pl2,pl3, vh[2], vh[3]);
                mma4(oacc[2*do2],   pa0,pa1,pa2,pa3, vl[0], vl[1]);
                mma4(oacc[2*do2+1], pa0,pa1,pa2,pa3, vl[2], vl[3]);
            }
        }
    }

    float* Os = (float*)(smem + STAGE0_OFF);
    float linv0 = 1.f / l0, linv1 = 1.f / l1;
    int r0q = wbase + (lane >> 2);
    int ddc = (lane & 3) * 2;
    #pragma unroll
    for (int d = 0; d < 8; d++) {
        Os[(d * 8 + ddc)     * OSTR + r0q]     = oacc[d][0] * linv0;
        Os[(d * 8 + ddc + 1) * OSTR + r0q]     = oacc[d][1] * linv0;
        Os[(d * 8 + ddc)     * OSTR + r0q + 8] = oacc[d][2] * linv1;
        Os[(d * 8 + ddc + 1) * OSTR + r0q + 8] = oacc[d][3] * linv1;
    }
    __syncthreads();

    {
        int q = tid >> 1;
        int ddb = (tid & 1) * 32;
        uint32_t hb[16], lb[16];
        #pragma unroll
        for (int d = 0; d < 32; d += 2) {
            float f0 = Os[(ddb + d)     * OSTR + q];
            float f1 = Os[(ddb + d + 1) * OSTR + q];
            uint32_t hp = packbf(f0, f1);
            hb[d >> 1] = hp;
            lb[d >> 1] = packbf(f0 - __uint_as_float(hp << 16),
                                f1 - __uint_as_float(hp & 0xFFFF0000u));
        }
        size_t base = ((size_t)b * NHW + qt * 128 + q) * NC + h * 64 + ddb;
        #pragma unroll
        for (int u = 0; u < 4; u++) {
            *(uint4*)(g_aoh + base + u * 8) = *(uint4*)&hb[u * 4];
            *(uint4*)(g_aol + base + u * 8) = *(uint4*)&lb[u * 4];
        }
    }
}

// ---------------------------------------------------------------------------
extern "C" void kernel_launch(void* const* d_in, const int* in_sizes, int n_in,
                              void* d_out, int out_size) {
    const float* x      = (const float*)d_in[0];
    const float* gn_w   = (const float*)d_in[1];
    const float* gn_b   = (const float*)d_in[2];
    const float* qkv_w  = (const float*)d_in[3];
    const float* qkv_b  = (const float*)d_in[4];
    const float* proj_w = (const float*)d_in[5];
    const float* proj_b = (const float*)d_in[6];
    float* out = (float*)d_out;

    cudaFuncSetAttribute(qkv_gemm3, cudaFuncAttributeMaxDynamicSharedMemorySize, G3_SMEM);
    cudaFuncSetAttribute(proj_gemm3, cudaFuncAttributeMaxDynamicSharedMemorySize, G3_SMEM);
    cudaFuncSetAttribute(attn_mma, cudaFuncAttributeMaxDynamicSharedMemorySize, ATTN_SMEM);

    __nv_bfloat16 *qwh, *qwl, *pwh, *pwl, *xh, *xl, *aoh, *aol, *qkvh, *qkvl;
    cudaGetSymbolAddress((void**)&qwh, g_qwh);
    cudaGetSymbolAddress((void**)&qwl, g_qwl);
    cudaGetSymbolAddress((void**)&pwh, g_pwh);
    cudaGetSymbolAddress((void**)&pwl, g_pwl);
    cudaGetSymbolAddress((void**)&xh,  g_xh);
    cudaGetSymbolAddress((void**)&xl,  g_xl);
    cudaGetSymbolAddress((void**)&aoh, g_aoh);
    cudaGetSymbolAddress((void**)&aol, g_aol);
    cudaGetSymbolAddress((void**)&qkvh, g_qkvh);
    cudaGetSymbolAddress((void**)&qkvl, g_qkvl);
    float *xnp;
    cudaGetSymbolAddress((void**)&xnp, g_xn);

    // 1. GroupNorm
    gn_kernel<<<NB * 8, 512>>>(x, gn_w, gn_b);
    // 2. Weight conversion (bf16 hi/lo)
    convert_w<<<(QC * NC + 255) / 256, 256>>>(qkv_w, qwh, qwl, QC * NC);
    convert_w<<<(NC * NC + 255) / 256, 256>>>(proj_w, pwh, pwl, NC * NC);
    // 3. Transpose+convert xn -> [b][n][c] bf16 hi/lo
    convert_t<<<dim3(NHW / 32, NC / 32, NB), dim3(32, 8)>>>(xnp, xh, xl);
    // 4. QKV GEMM v3 (64x64 warp tiles), writes bf16 hi/lo (Q scaled)
    qkv_gemm3<<<dim3(NHW / 128, QC / 128, NB), 128, G3_SMEM>>>(
        qwh, qwl, xh, xl, qkv_b, qkvh, qkvl);
    // 5. Flash attention (mma.sync), writes g_aoh/g_aol in [b][n][c]
    attn_mma<<<dim3(NHW / 128, NHEADS, NB), 256, ATTN_SMEM>>>();
    // 6. Proj GEMM v3 + bias + residual
    proj_gemm3<<<dim3(NHW / 128, NC / 128, NB), 128, G3_SMEM>>>(
        pwh, pwl, aoh, aol, proj_b, x, out);
}